// round 9
// baseline (speedup 1.0000x reference)
#include <cuda_runtime.h>
#include <cuda_bf16.h>
#include <cstdint>
#include <math.h>

#define HW    9216
#define CH    256
#define NB    2

// ---------------- scratch ----------------
__device__ float g_f[8ull * 9 * HW];               // [nb][o][HW] softmax tap weights
__device__ float g_u[(size_t)NB * 384 * HW];       // [n][br*96 + o*9+tap][HW]
__device__ float g_z[10ull * HW * CH + 400000];    // [b*2+n][p][c]
__device__ float g_y[(size_t)NB * HW * CH];        // [n][p][c]
__device__ float g_bpart[NB * 1152 * 64];
__device__ float g_stats[NB * 32 * 2];
__device__ __nv_bfloat16 g_w[5ull * 256 * 512];    // [b][m][k'=512: per 32-grp hi|lo]
__device__ __nv_bfloat16 g_xT[(size_t)NB * HW * 512]; // [n][p][k']
__device__ __nv_bfloat16 g_wl2[384ull * 512];      // [m][k']

// ---------------- helpers ----------------
__device__ __forceinline__ uint32_t smem_u32(const void* p) {
    uint32_t a;
    asm("{ .reg .u64 t; cvta.to.shared.u64 t, %1; cvt.u32.u64 %0, t; }" : "=r"(a) : "l"(p));
    return a;
}
__device__ __forceinline__ void ldmatrix_x4(uint32_t& r0, uint32_t& r1, uint32_t& r2, uint32_t& r3, uint32_t addr) {
    asm volatile("ldmatrix.sync.aligned.m8n8.x4.shared.b16 {%0,%1,%2,%3}, [%4];"
        : "=r"(r0), "=r"(r1), "=r"(r2), "=r"(r3) : "r"(addr));
}
__device__ __forceinline__ void mma_bf16(float* c, const uint32_t* a, uint32_t b0, uint32_t b1) {
    asm volatile("mma.sync.aligned.m16n8k16.row.col.f32.bf16.bf16.f32 "
        "{%0,%1,%2,%3}, {%4,%5,%6,%7}, {%8,%9}, {%0,%1,%2,%3};"
        : "+f"(c[0]), "+f"(c[1]), "+f"(c[2]), "+f"(c[3])
        : "r"(a[0]), "r"(a[1]), "r"(a[2]), "r"(a[3]), "r"(b0), "r"(b1));
}
__device__ __forceinline__ void cp_async16(uint32_t saddr, const void* gaddr) {
    asm volatile("cp.async.cg.shared.global [%0], [%1], 16;" :: "r"(saddr), "l"(gaddr));
}
// k' mapping: channel c, sel -> (c>>5)*64 + sel*32 + (c&31)
__device__ __forceinline__ int kprime(int c, int sel) {
    return ((c >> 5) << 6) + sel * 32 + (c & 31);
}

// ---------------- prep: split W (proj), interleaved hi/lo ----------------
__global__ void __launch_bounds__(256) wsplit_kernel(const float* __restrict__ wproj)
{
    int idx = blockIdx.x * 256 + threadIdx.x;
    if (idx >= 5 * 65536) return;
    int b = idx >> 16, rem = idx & 65535;
    int m = rem >> 8, c = rem & 255;
    float w = wproj[m * 1280 + b * 256 + c];
    __nv_bfloat16 hi = __float2bfloat16(w);
    __nv_bfloat16 lo = __float2bfloat16(w - __bfloat162float(hi));
    size_t base = ((size_t)b * 256 + m) * 512;
    g_w[base + kprime(c, 0)] = hi;
    g_w[base + kprime(c, 1)] = lo;
}

// ---------------- prep: logits weights -> A[384][512] ----------------
__global__ void __launch_bounds__(256) wl2split_kernel(
    const float* __restrict__ wa, const float* __restrict__ wb,
    const float* __restrict__ wc, const float* __restrict__ wd)
{
    int idx = blockIdx.x * 256 + threadIdx.x;       // 384*256
    if (idx >= 98304) return;
    int c = idx & 255, m = idx >> 8;
    int br = m / 96, row = m - br * 96;
    float w = 0.f;
    if (row < 81) {
        int o = row / 9, tap = row - o * 9;
        const float* wp = (br == 0) ? wa : (br == 1) ? wb : (br == 2) ? wc : wd;
        w = wp[(o * 256 + c) * 9 + tap];
    }
    __nv_bfloat16 hi = __float2bfloat16(w);
    __nv_bfloat16 lo = __float2bfloat16(w - __bfloat162float(hi));
    size_t base = (size_t)m * 512;
    g_wl2[base + kprime(c, 0)] = hi;
    g_wl2[base + kprime(c, 1)] = lo;
}

// ---------------- prep: transpose x to [p][k'] interleaved hi/lo ----------------
__global__ void __launch_bounds__(256) xsplit_kernel(const float* __restrict__ x)
{
    __shared__ float t[32][33];
    int p0 = blockIdx.x * 32, k0 = blockIdx.y * 32, n = blockIdx.z;
    int tx = threadIdx.x, ty = threadIdx.y;
#pragma unroll
    for (int r = 0; r < 4; r++)
        t[ty + 8 * r][tx] = x[((size_t)(n * 256 + k0 + ty + 8 * r)) * HW + p0 + tx];
    __syncthreads();
#pragma unroll
    for (int r = 0; r < 4; r++) {
        int p = p0 + ty + 8 * r, c = k0 + tx;
        float v = t[tx][ty + 8 * r];
        __nv_bfloat16 hi = __float2bfloat16(v);
        __nv_bfloat16 lo = __float2bfloat16(v - __bfloat162float(hi));
        size_t base = ((size_t)n * HW + p) * 512;
        g_xT[base + kprime(c, 0)] = hi;
        g_xT[base + kprime(c, 1)] = lo;
    }
}

// ================= GEMM tile: 64m x 128p; 8 kc of 32 channels (hi+lo resident)
// smem per stage 24KB: A[64][128B] + B[128][128B]; 3 stages = 72KB (3 CTAs/SM)
// warps 8: warp_m = wid&1 (32m), warp_n = wid>>1 (32p)
// Within a 128B row: u 0..3 = hi k-halves, u 4..7 = lo k-halves.

struct MmaCtx {
    uint32_t sbase;
    int tid, lane, warp_m, warp_n;
    float acc[2][4][4];
    __device__ __forceinline__ void init(uint32_t sb, int t) {
        sbase = sb; tid = t; lane = t & 31;
        int wid = t >> 5;
        warp_m = wid & 1; warp_n = wid >> 1;
#pragma unroll
        for (int i = 0; i < 2; i++)
#pragma unroll
            for (int j = 0; j < 4; j++)
#pragma unroll
                for (int r = 0; r < 4; r++) acc[i][j][r] = 0.f;
    }
    __device__ __forceinline__ void fill(int buf, const char* Ag, const char* Bg) {
        uint32_t aOff = buf * 24576u;
        uint32_t bOff = 8192u + buf * 24576u;
#pragma unroll
        for (int r = 0; r < 2; r++) {
            int idx = tid + 256 * r;          // 0..511
            int row = idx >> 3, u = idx & 7;
            uint32_t sw = row * 128 + ((u ^ (row & 7)) << 4);
            cp_async16(sbase + aOff + sw, Ag + (size_t)row * 1024 + u * 16);
        }
#pragma unroll
        for (int r = 0; r < 4; r++) {
            int idx = tid + 256 * r;          // 0..1023
            int row = idx >> 3, u = idx & 7;
            uint32_t sw = row * 128 + ((u ^ (row & 7)) << 4);
            cp_async16(sbase + bOff + sw, Bg + (size_t)row * 1024 + u * 16);
        }
        asm volatile("cp.async.commit_group;");
    }
    __device__ __forceinline__ void compute(int buf) {
        uint32_t aB = sbase + buf * 24576u;
        uint32_t bB = sbase + 8192u + buf * 24576u;
#pragma unroll
        for (int ks = 0; ks < 2; ks++) {
            int u0h = ks * 2 + (lane >> 4);
            int u0l = u0h + 4;
            uint32_t a[2][4], bh[2][4], bl[2][4];
#pragma unroll
            for (int q = 0; q < 2; q++) {
                int row = warp_n * 32 + q * 16 + (lane & 15);
                uint32_t rb = bB + row * 128;
                ldmatrix_x4(bh[q][0], bh[q][1], bh[q][2], bh[q][3], rb + (((unsigned)(u0h ^ (row & 7))) << 4));
                ldmatrix_x4(bl[q][0], bl[q][1], bl[q][2], bl[q][3], rb + (((unsigned)(u0l ^ (row & 7))) << 4));
            }
#pragma unroll
            for (int mi = 0; mi < 2; mi++) {
                int row = warp_m * 32 + mi * 16 + (lane & 15);
                ldmatrix_x4(a[mi][0], a[mi][1], a[mi][2], a[mi][3],
                            aB + row * 128 + (((unsigned)(u0h ^ (row & 7))) << 4));
            }
#pragma unroll
            for (int mi = 0; mi < 2; mi++)
#pragma unroll
                for (int nj = 0; nj < 4; nj++) {
                    int q = nj >> 1, pr = nj & 1;
                    mma_bf16(acc[mi][nj], a[mi], bh[q][pr], bh[q][pr + 2]);
                    mma_bf16(acc[mi][nj], a[mi], bl[q][pr], bl[q][pr + 2]);
                }
#pragma unroll
            for (int mi = 0; mi < 2; mi++) {
                int row = warp_m * 32 + mi * 16 + (lane & 15);
                ldmatrix_x4(a[mi][0], a[mi][1], a[mi][2], a[mi][3],
                            aB + row * 128 + (((unsigned)(u0l ^ (row & 7))) << 4));
            }
#pragma unroll
            for (int mi = 0; mi < 2; mi++)
#pragma unroll
                for (int nj = 0; nj < 4; nj++) {
                    int q = nj >> 1, pr = nj & 1;
                    mma_bf16(acc[mi][nj], a[mi], bh[q][pr], bh[q][pr + 2]);
                }
        }
    }
    __device__ __forceinline__ void run(const char* Abase, const char* Bbase) {
        fill(0, Abase, Bbase);
        fill(1, Abase + 128, Bbase + 128);
        for (int i = 0; i < 8; i++) {
            if (i < 6) asm volatile("cp.async.wait_group 1;");
            else       asm volatile("cp.async.wait_group 0;");
            __syncthreads();
            compute(i % 3);
            if (i + 2 < 8) fill((i + 2) % 3, Abase + (i + 2) * 128, Bbase + (i + 2) * 128);
        }
        __syncthreads();
    }
    // stage[p(0..127)][m pitch 68]
    __device__ __forceinline__ void stage_out(float* stage) {
#pragma unroll
        for (int mi = 0; mi < 2; mi++)
#pragma unroll
            for (int nj = 0; nj < 4; nj++)
#pragma unroll
                for (int r = 0; r < 4; r++) {
                    int p = warp_n * 32 + nj * 8 + 2 * (lane & 3) + (r & 1);
                    int m = warp_m * 32 + mi * 16 + (lane >> 2) + ((r >> 1) << 3);
                    stage[p * 68 + m] = acc[mi][nj][r];
                }
    }
};

// ---------------- 1) U-GEMM: grid (72, 6, 2) ----------------
__global__ void __launch_bounds__(256, 3) gemm_u_kernel()
{
    extern __shared__ char dsm[];
    MmaCtx g;
    g.init(smem_u32(dsm), threadIdx.x);
    int pbase = blockIdx.x * 128;
    int mbase = blockIdx.y * 64;
    int n = blockIdx.z;

    g.run((const char*)g_wl2 + (size_t)mbase * 1024,
          (const char*)g_xT + ((size_t)n * HW + pbase) * 1024);

    float* stage = (float*)dsm;
    g.stage_out(stage);
    __syncthreads();
#pragma unroll
    for (int rr = 0; rr < 8; rr++) {
        int idx = threadIdx.x + 256 * rr;      // 0..2047
        int m = idx >> 5, p4 = (idx & 31) * 4;
        float4 v = make_float4(stage[p4 * 68 + m], stage[(p4 + 1) * 68 + m],
                               stage[(p4 + 2) * 68 + m], stage[(p4 + 3) * 68 + m]);
        *(float4*)(g_u + ((size_t)n * 384 + mbase + m) * HW + pbase + p4) = v;
    }
}

// ---------------- 2) gather taps + softmax ----------------
__global__ void __launch_bounds__(256) gathersoftmax_kernel()
{
    int id = blockIdx.x * 256 + threadIdx.x;
    int p = id % HW;
    int nb = id / HW;
    int n = nb >> 2, br = nb & 3;
    int d = (br == 0) ? 1 : (br == 1) ? 4 : (br == 2) ? 8 : 12;
    int y = p / 96, x = p - y * 96;

    int po[9];
#pragma unroll
    for (int t = 0; t < 9; t++) {
        int yy = y + (t / 3 - 1) * d;
        int xx = x + (t % 3 - 1) * d;
        po[t] = (((unsigned)yy < 96u) && ((unsigned)xx < 96u)) ? (yy * 96 + xx) : -1;
    }

    const float* ub = g_u + ((size_t)n * 384 + br * 96) * HW;
    float l[9];
#pragma unroll
    for (int o = 0; o < 9; o++) {
        float s = 0.f;
#pragma unroll
        for (int t = 0; t < 9; t++)
            if (po[t] >= 0) s += ub[(size_t)(o * 9 + t) * HW + po[t]];
        l[o] = s;
    }
    float m = l[0];
#pragma unroll
    for (int o = 1; o < 9; o++) m = fmaxf(m, l[o]);
    float s = 0.f;
#pragma unroll
    for (int o = 0; o < 9; o++) { l[o] = expf(l[o] - m); s += l[o]; }
    float inv = 1.f / s;
#pragma unroll
    for (int o = 0; o < 9; o++)
        g_f[((size_t)nb * 9 + o) * HW + p] = l[o] * inv;
}

// ---------------- 3) proj GEMM: grid (72, 4, 10) ----------------
__global__ void __launch_bounds__(256, 3) gemm_mma_kernel()
{
    extern __shared__ char dsm[];
    MmaCtx g;
    g.init(smem_u32(dsm), threadIdx.x);
    int pbase = blockIdx.x * 128;
    int mbase = blockIdx.y * 64;
    int bn = blockIdx.z;
    int b = bn >> 1, n = bn & 1;

    g.run((const char*)g_w + ((size_t)b * 256 + mbase) * 1024,
          (const char*)g_xT + ((size_t)n * HW + pbase) * 1024);

    float* stage = (float*)dsm;
    g.stage_out(stage);
    __syncthreads();
    float* zo = (float*)g_z + ((size_t)bn * HW + pbase) * 256 + mbase;
#pragma unroll
    for (int r = 0; r < 8; r++) {
        int idx = threadIdx.x + 256 * r;       // 0..2047
        int px = idx >> 4, c4 = (idx & 15) * 4;
        float4 v = *(float4*)&stage[px * 68 + c4];
        *(float4*)(zo + (size_t)px * 256 + c4) = v;
    }
}

// ---------------- 4) combine ----------------
__global__ void __launch_bounds__(512) combine_kernel(const float* __restrict__ bias)
{
    int tid = threadIdx.x;
    int n = blockIdx.y;
    int p0 = blockIdx.x * 8;
    int warp = tid >> 5, lane = tid & 31;
    int pi = warp >> 1, half = warp & 1;
    int p = p0 + pi;
    int c = half * 128 + lane * 4;

    __shared__ float fsw[8][40];
    __shared__ int   pofs[8][40];
    __shared__ float bp_s[16][16];
    __shared__ float bp_q[16][16];

    if (tid < 288) {
        int pi2 = tid / 36, j = tid - pi2 * 36;
        int br = j / 9, k = j - br * 9;
        int d = (br == 0) ? 1 : (br == 1) ? 4 : (br == 2) ? 8 : 12;
        int pg = p0 + pi2;
        int yy = pg / 96 + (k / 3 - 1) * d;
        int xx = pg % 96 + (k % 3 - 1) * d;
        bool v = ((unsigned)yy < 96u) && ((unsigned)xx < 96u);
        fsw[pi2][j]  = v ? g_f[((size_t)(n * 4 + br) * 9 + k) * HW + pg] : 0.f;
        pofs[pi2][j] = (((br + 1) * 2 + n) * HW + (v ? (yy * 96 + xx) : 0)) * 256;
    }
    __syncthreads();

    float4 b4 = *(const float4*)(bias + c);
    float4 z4 = *(const float4*)(g_z + ((size_t)n * HW + p) * 256 + c);
    float a0 = z4.x + b4.x, a1 = z4.y + b4.y, a2 = z4.z + b4.z, a3 = z4.w + b4.w;

#pragma unroll 4
    for (int j = 0; j < 36; j++) {
        float f = fsw[pi][j];
        const float* zp = g_z + (size_t)pofs[pi][j] + c;
        float4 v = *(const float4*)zp;
        a0 = fmaf(f, v.x, a0); a1 = fmaf(f, v.y, a1);
        a2 = fmaf(f, v.z, a2); a3 = fmaf(f, v.w, a3);
    }
    *(float4*)(g_y + ((size_t)n * HW + p) * 256 + c) = make_float4(a0, a1, a2, a3);

    float s = a0 + a1 + a2 + a3;
    float q = a0 * a0 + a1 * a1 + a2 * a2 + a3 * a3;
    s += __shfl_xor_sync(0xffffffffu, s, 1);
    q += __shfl_xor_sync(0xffffffffu, q, 1);
    if ((lane & 1) == 0) { bp_s[warp][lane >> 1] = s; bp_q[warp][lane >> 1] = q; }
    __syncthreads();
    if (tid < 64) {
        int g = tid >> 1, isq = tid & 1;
        int hf = g >> 4, gi = g & 15;
        float acc = 0.f;
#pragma unroll
        for (int pi2 = 0; pi2 < 8; pi2++)
            acc += isq ? bp_q[pi2 * 2 + hf][gi] : bp_s[pi2 * 2 + hf][gi];
        g_bpart[((size_t)n * 1152 + blockIdx.x) * 64 + tid] = acc;
    }
}

// ---------------- 5) GN stats ----------------
__global__ void __launch_bounds__(128) stats_kernel()
{
    int b = blockIdx.x;
    int n = b >> 5, g = b & 31;
    int tid = threadIdx.x;
    float s = 0.f, q = 0.f;
    for (int i = tid; i < 1152; i += 128) {
        size_t base = ((size_t)n * 1152 + i) * 64 + g * 2;
        s += g_bpart[base];
        q += g_bpart[base + 1];
    }
    __shared__ float ss[128], sq[128];
    ss[tid] = s; sq[tid] = q;
    __syncthreads();
    for (int off = 64; off > 0; off >>= 1) {
        if (tid < off) { ss[tid] += ss[tid + off]; sq[tid] += sq[tid + off]; }
        __syncthreads();
    }
    if (tid == 0) {
        const float invN = 1.f / 73728.f;
        float mean = ss[0] * invN;
        float var  = sq[0] * invN - mean * mean;
        g_stats[b * 2]     = mean;
        g_stats[b * 2 + 1] = rsqrtf(var + 1e-5f);
    }
}

// ---------------- 6) transpose + GN affine + relu ----------------
__global__ void __launch_bounds__(256) normT_kernel(
    const float* __restrict__ gamma, const float* __restrict__ beta,
    float* __restrict__ out)
{
    __shared__ float t[32][33];
    int p0 = blockIdx.x * 32, c0 = blockIdx.y * 32, n = blockIdx.z;
    int tx = threadIdx.x, ty = threadIdx.y;
#pragma unroll
    for (int r = 0; r < 4; r++)
        t[ty + 8 * r][tx] = g_y[((size_t)n * HW + p0 + ty + 8 * r) * 256 + c0 + tx];
    __syncthreads();
#pragma unroll
    for (int r = 0; r < 4; r++) {
        int c = c0 + ty + 8 * r, p = p0 + tx;
        int g = c >> 3;
        float mean = g_stats[(n * 32 + g) * 2];
        float rstd = g_stats[(n * 32 + g) * 2 + 1];
        float ga = gamma[c] * rstd;
        float be = beta[c] - mean * ga;
        float v = t[tx][ty + 8 * r];
        out[((size_t)n * 256 + c) * HW + p] = fmaxf(fmaf(v, ga, be), 0.f);
    }
}

// ---------------- launch ----------------
extern "C" void kernel_launch(void* const* d_in, const int* in_sizes, int n_in,
                              void* d_out, int out_size)
{
    const float* x     = (const float*)d_in[0];
    const float* wa    = (const float*)d_in[1];
    const float* wb    = (const float*)d_in[2];
    const float* wc    = (const float*)d_in[3];
    const float* wd    = (const float*)d_in[4];
    const float* wproj = (const float*)d_in[5];
    const float* bproj = (const float*)d_in[6];
    const float* gamma = (const float*)d_in[7];
    const float* beta  = (const float*)d_in[8];
    float* out = (float*)d_out;

    cudaFuncSetAttribute(gemm_mma_kernel, cudaFuncAttributeMaxDynamicSharedMemorySize, 73728);
    cudaFuncSetAttribute(gemm_u_kernel,   cudaFuncAttributeMaxDynamicSharedMemorySize, 73728);

    wsplit_kernel<<<1280, 256>>>(wproj);
    wl2split_kernel<<<384, 256>>>(wa, wb, wc, wd);
    xsplit_kernel<<<dim3(288, 8, 2), dim3(32, 8)>>>(x);
    gemm_u_kernel<<<dim3(72, 6, 2), 256, 73728>>>();
    gathersoftmax_kernel<<<288, 256>>>();
    gemm_mma_kernel<<<dim3(72, 4, 10), 256, 73728>>>();
    combine_kernel<<<dim3(1152, 2), 512>>>(bproj);
    stats_kernel<<<64, 128>>>();
    normT_kernel<<<dim3(288, 8, 2), dim3(32, 8)>>>(gamma, beta, out);
}

// round 10
// speedup vs baseline: 1.0057x; 1.0057x over previous
#include <cuda_runtime.h>
#include <cuda_bf16.h>
#include <cstdint>
#include <math.h>

#define HW    9216
#define CH    256
#define NB    2

// ---------------- scratch ----------------
__device__ float g_f[8ull * 9 * HW];               // [nb][o][HW] softmax tap weights
__device__ float g_u[(size_t)NB * 384 * HW];       // [n][br*96 + o*9+tap][HW]
__device__ float g_z[10ull * HW * CH + 400000];    // [b*2+n][p][c]
__device__ float g_y[(size_t)NB * HW * CH];        // [n][p][c]
__device__ float g_bpart[NB * 1152 * 64];
__device__ float g_stats[NB * 32 * 2];
__device__ __nv_bfloat16 g_w[5ull * 256 * 512];    // [b][m][k'=512: per 32-grp hi|lo]
__device__ __nv_bfloat16 g_xT[(size_t)NB * HW * 512]; // [n][p][k']
__device__ __nv_bfloat16 g_wl2[384ull * 512];      // [m][k']

// ---------------- helpers ----------------
__device__ __forceinline__ uint32_t smem_u32(const void* p) {
    uint32_t a;
    asm("{ .reg .u64 t; cvta.to.shared.u64 t, %1; cvt.u32.u64 %0, t; }" : "=r"(a) : "l"(p));
    return a;
}
__device__ __forceinline__ void ldmatrix_x4(uint32_t& r0, uint32_t& r1, uint32_t& r2, uint32_t& r3, uint32_t addr) {
    asm volatile("ldmatrix.sync.aligned.m8n8.x4.shared.b16 {%0,%1,%2,%3}, [%4];"
        : "=r"(r0), "=r"(r1), "=r"(r2), "=r"(r3) : "r"(addr));
}
__device__ __forceinline__ void mma_bf16(float* c, const uint32_t* a, uint32_t b0, uint32_t b1) {
    asm volatile("mma.sync.aligned.m16n8k16.row.col.f32.bf16.bf16.f32 "
        "{%0,%1,%2,%3}, {%4,%5,%6,%7}, {%8,%9}, {%0,%1,%2,%3};"
        : "+f"(c[0]), "+f"(c[1]), "+f"(c[2]), "+f"(c[3])
        : "r"(a[0]), "r"(a[1]), "r"(a[2]), "r"(a[3]), "r"(b0), "r"(b1));
}
__device__ __forceinline__ void cp_async16(uint32_t saddr, const void* gaddr) {
    asm volatile("cp.async.cg.shared.global [%0], [%1], 16;" :: "r"(saddr), "l"(gaddr));
}
// k' mapping: channel c, sel -> (c>>5)*64 + sel*32 + (c&31)
__device__ __forceinline__ int kprime(int c, int sel) {
    return ((c >> 5) << 6) + sel * 32 + (c & 31);
}

// ---------------- prep: split W (proj), interleaved hi/lo ----------------
__global__ void __launch_bounds__(256) wsplit_kernel(const float* __restrict__ wproj)
{
    int idx = blockIdx.x * 256 + threadIdx.x;
    if (idx >= 5 * 65536) return;
    int b = idx >> 16, rem = idx & 65535;
    int m = rem >> 8, c = rem & 255;
    float w = wproj[m * 1280 + b * 256 + c];
    __nv_bfloat16 hi = __float2bfloat16(w);
    __nv_bfloat16 lo = __float2bfloat16(w - __bfloat162float(hi));
    size_t base = ((size_t)b * 256 + m) * 512;
    g_w[base + kprime(c, 0)] = hi;
    g_w[base + kprime(c, 1)] = lo;
}

// ---------------- prep: logits weights -> A[384][512] ----------------
__global__ void __launch_bounds__(256) wl2split_kernel(
    const float* __restrict__ wa, const float* __restrict__ wb,
    const float* __restrict__ wc, const float* __restrict__ wd)
{
    int idx = blockIdx.x * 256 + threadIdx.x;       // 384*256
    if (idx >= 98304) return;
    int c = idx & 255, m = idx >> 8;
    int br = m / 96, row = m - br * 96;
    float w = 0.f;
    if (row < 81) {
        int o = row / 9, tap = row - o * 9;
        const float* wp = (br == 0) ? wa : (br == 1) ? wb : (br == 2) ? wc : wd;
        w = wp[(o * 256 + c) * 9 + tap];
    }
    __nv_bfloat16 hi = __float2bfloat16(w);
    __nv_bfloat16 lo = __float2bfloat16(w - __bfloat162float(hi));
    size_t base = (size_t)m * 512;
    g_wl2[base + kprime(c, 0)] = hi;
    g_wl2[base + kprime(c, 1)] = lo;
}

// ---------------- prep: transpose x to [p][k'] interleaved hi/lo ----------------
__global__ void __launch_bounds__(256) xsplit_kernel(const float* __restrict__ x)
{
    __shared__ float t[32][33];
    int p0 = blockIdx.x * 32, k0 = blockIdx.y * 32, n = blockIdx.z;
    int tx = threadIdx.x, ty = threadIdx.y;
#pragma unroll
    for (int r = 0; r < 4; r++)
        t[ty + 8 * r][tx] = x[((size_t)(n * 256 + k0 + ty + 8 * r)) * HW + p0 + tx];
    __syncthreads();
#pragma unroll
    for (int r = 0; r < 4; r++) {
        int p = p0 + ty + 8 * r, c = k0 + tx;
        float v = t[tx][ty + 8 * r];
        __nv_bfloat16 hi = __float2bfloat16(v);
        __nv_bfloat16 lo = __float2bfloat16(v - __bfloat162float(hi));
        size_t base = ((size_t)n * HW + p) * 512;
        g_xT[base + kprime(c, 0)] = hi;
        g_xT[base + kprime(c, 1)] = lo;
    }
}

// ================= GEMM tile: 64m x 128p; 8 kc of 32 channels (hi+lo resident)
// smem per stage 24KB: A[64][128B] + B[128][128B]; 3 stages = 72KB (3 CTAs/SM)
// warps 8: warp_m = wid&1 (32m), warp_n = wid>>1 (32p)
// Within a 128B row: u 0..3 = hi k-halves, u 4..7 = lo k-halves.

struct MmaCtx {
    uint32_t sbase;
    int tid, lane, warp_m, warp_n;
    float acc[2][4][4];
    __device__ __forceinline__ void init(uint32_t sb, int t) {
        sbase = sb; tid = t; lane = t & 31;
        int wid = t >> 5;
        warp_m = wid & 1; warp_n = wid >> 1;
#pragma unroll
        for (int i = 0; i < 2; i++)
#pragma unroll
            for (int j = 0; j < 4; j++)
#pragma unroll
                for (int r = 0; r < 4; r++) acc[i][j][r] = 0.f;
    }
    __device__ __forceinline__ void fill(int buf, const char* Ag, const char* Bg) {
        uint32_t aOff = buf * 24576u;
        uint32_t bOff = 8192u + buf * 24576u;
#pragma unroll
        for (int r = 0; r < 2; r++) {
            int idx = tid + 256 * r;          // 0..511
            int row = idx >> 3, u = idx & 7;
            uint32_t sw = row * 128 + ((u ^ (row & 7)) << 4);
            cp_async16(sbase + aOff + sw, Ag + (size_t)row * 1024 + u * 16);
        }
#pragma unroll
        for (int r = 0; r < 4; r++) {
            int idx = tid + 256 * r;          // 0..1023
            int row = idx >> 3, u = idx & 7;
            uint32_t sw = row * 128 + ((u ^ (row & 7)) << 4);
            cp_async16(sbase + bOff + sw, Bg + (size_t)row * 1024 + u * 16);
        }
        asm volatile("cp.async.commit_group;");
    }
    __device__ __forceinline__ void compute(int buf) {
        uint32_t aB = sbase + buf * 24576u;
        uint32_t bB = sbase + 8192u + buf * 24576u;
#pragma unroll
        for (int ks = 0; ks < 2; ks++) {
            int u0h = ks * 2 + (lane >> 4);
            int u0l = u0h + 4;
            uint32_t a[2][4], bh[2][4], bl[2][4];
#pragma unroll
            for (int q = 0; q < 2; q++) {
                int row = warp_n * 32 + q * 16 + (lane & 15);
                uint32_t rb = bB + row * 128;
                ldmatrix_x4(bh[q][0], bh[q][1], bh[q][2], bh[q][3], rb + (((unsigned)(u0h ^ (row & 7))) << 4));
                ldmatrix_x4(bl[q][0], bl[q][1], bl[q][2], bl[q][3], rb + (((unsigned)(u0l ^ (row & 7))) << 4));
            }
#pragma unroll
            for (int mi = 0; mi < 2; mi++) {
                int row = warp_m * 32 + mi * 16 + (lane & 15);
                ldmatrix_x4(a[mi][0], a[mi][1], a[mi][2], a[mi][3],
                            aB + row * 128 + (((unsigned)(u0h ^ (row & 7))) << 4));
            }
#pragma unroll
            for (int mi = 0; mi < 2; mi++)
#pragma unroll
                for (int nj = 0; nj < 4; nj++) {
                    int q = nj >> 1, pr = nj & 1;
                    mma_bf16(acc[mi][nj], a[mi], bh[q][pr], bh[q][pr + 2]);
                    mma_bf16(acc[mi][nj], a[mi], bl[q][pr], bl[q][pr + 2]);
                }
#pragma unroll
            for (int mi = 0; mi < 2; mi++) {
                int row = warp_m * 32 + mi * 16 + (lane & 15);
                ldmatrix_x4(a[mi][0], a[mi][1], a[mi][2], a[mi][3],
                            aB + row * 128 + (((unsigned)(u0l ^ (row & 7))) << 4));
            }
#pragma unroll
            for (int mi = 0; mi < 2; mi++)
#pragma unroll
                for (int nj = 0; nj < 4; nj++) {
                    int q = nj >> 1, pr = nj & 1;
                    mma_bf16(acc[mi][nj], a[mi], bh[q][pr], bh[q][pr + 2]);
                }
        }
    }
    __device__ __forceinline__ void run(const char* Abase, const char* Bbase) {
        fill(0, Abase, Bbase);
        fill(1, Abase + 128, Bbase + 128);
        for (int i = 0; i < 8; i++) {
            if (i < 6) asm volatile("cp.async.wait_group 1;");
            else       asm volatile("cp.async.wait_group 0;");
            __syncthreads();
            compute(i % 3);
            if (i + 2 < 8) fill((i + 2) % 3, Abase + (i + 2) * 128, Bbase + (i + 2) * 128);
        }
        __syncthreads();
    }
    // stage[p(0..127)][m pitch 68]
    __device__ __forceinline__ void stage_out(float* stage) {
#pragma unroll
        for (int mi = 0; mi < 2; mi++)
#pragma unroll
            for (int nj = 0; nj < 4; nj++)
#pragma unroll
                for (int r = 0; r < 4; r++) {
                    int p = warp_n * 32 + nj * 8 + 2 * (lane & 3) + (r & 1);
                    int m = warp_m * 32 + mi * 16 + (lane >> 2) + ((r >> 1) << 3);
                    stage[p * 68 + m] = acc[mi][nj][r];
                }
    }
};

// ---------------- 1) U-GEMM: grid (72, 6, 2) ----------------
__global__ void __launch_bounds__(256, 3) gemm_u_kernel()
{
    extern __shared__ char dsm[];
    MmaCtx g;
    g.init(smem_u32(dsm), threadIdx.x);
    int pbase = blockIdx.x * 128;
    int mbase = blockIdx.y * 64;
    int n = blockIdx.z;

    g.run((const char*)g_wl2 + (size_t)mbase * 1024,
          (const char*)g_xT + ((size_t)n * HW + pbase) * 1024);

    float* stage = (float*)dsm;
    g.stage_out(stage);
    __syncthreads();
#pragma unroll
    for (int rr = 0; rr < 8; rr++) {
        int idx = threadIdx.x + 256 * rr;      // 0..2047
        int m = idx >> 5, p4 = (idx & 31) * 4;
        float4 v = make_float4(stage[p4 * 68 + m], stage[(p4 + 1) * 68 + m],
                               stage[(p4 + 2) * 68 + m], stage[(p4 + 3) * 68 + m]);
        *(float4*)(g_u + ((size_t)n * 384 + mbase + m) * HW + pbase + p4) = v;
    }
}

// ---------------- 2) gather taps + softmax ----------------
__global__ void __launch_bounds__(256) gathersoftmax_kernel()
{
    int id = blockIdx.x * 256 + threadIdx.x;
    int p = id % HW;
    int nb = id / HW;
    int n = nb >> 2, br = nb & 3;
    int d = (br == 0) ? 1 : (br == 1) ? 4 : (br == 2) ? 8 : 12;
    int y = p / 96, x = p - y * 96;

    int po[9];
#pragma unroll
    for (int t = 0; t < 9; t++) {
        int yy = y + (t / 3 - 1) * d;
        int xx = x + (t % 3 - 1) * d;
        po[t] = (((unsigned)yy < 96u) && ((unsigned)xx < 96u)) ? (yy * 96 + xx) : -1;
    }

    const float* ub = g_u + ((size_t)n * 384 + br * 96) * HW;
    float l[9];
#pragma unroll
    for (int o = 0; o < 9; o++) {
        float s = 0.f;
#pragma unroll
        for (int t = 0; t < 9; t++)
            if (po[t] >= 0) s += ub[(size_t)(o * 9 + t) * HW + po[t]];
        l[o] = s;
    }
    float m = l[0];
#pragma unroll
    for (int o = 1; o < 9; o++) m = fmaxf(m, l[o]);
    float s = 0.f;
#pragma unroll
    for (int o = 0; o < 9; o++) { l[o] = expf(l[o] - m); s += l[o]; }
    float inv = 1.f / s;
#pragma unroll
    for (int o = 0; o < 9; o++)
        g_f[((size_t)nb * 9 + o) * HW + p] = l[o] * inv;
}

// ---------------- 3) proj GEMM: grid (72, 4, 10) ----------------
__global__ void __launch_bounds__(256, 3) gemm_mma_kernel()
{
    extern __shared__ char dsm[];
    MmaCtx g;
    g.init(smem_u32(dsm), threadIdx.x);
    int pbase = blockIdx.x * 128;
    int mbase = blockIdx.y * 64;
    int bn = blockIdx.z;
    int b = bn >> 1, n = bn & 1;

    g.run((const char*)g_w + ((size_t)b * 256 + mbase) * 1024,
          (const char*)g_xT + ((size_t)n * HW + pbase) * 1024);

    float* stage = (float*)dsm;
    g.stage_out(stage);
    __syncthreads();
    float* zo = (float*)g_z + ((size_t)bn * HW + pbase) * 256 + mbase;
#pragma unroll
    for (int r = 0; r < 8; r++) {
        int idx = threadIdx.x + 256 * r;       // 0..2047
        int px = idx >> 4, c4 = (idx & 15) * 4;
        float4 v = *(float4*)&stage[px * 68 + c4];
        *(float4*)(zo + (size_t)px * 256 + c4) = v;
    }
}

// ---------------- 4) combine ----------------
__global__ void __launch_bounds__(512) combine_kernel(const float* __restrict__ bias)
{
    int tid = threadIdx.x;
    int n = blockIdx.y;
    int p0 = blockIdx.x * 8;
    int warp = tid >> 5, lane = tid & 31;
    int pi = warp >> 1, half = warp & 1;
    int p = p0 + pi;
    int c = half * 128 + lane * 4;

    __shared__ float fsw[8][40];
    __shared__ int   pofs[8][40];
    __shared__ float bp_s[16][16];
    __shared__ float bp_q[16][16];

    if (tid < 288) {
        int pi2 = tid / 36, j = tid - pi2 * 36;
        int br = j / 9, k = j - br * 9;
        int d = (br == 0) ? 1 : (br == 1) ? 4 : (br == 2) ? 8 : 12;
        int pg = p0 + pi2;
        int yy = pg / 96 + (k / 3 - 1) * d;
        int xx = pg % 96 + (k % 3 - 1) * d;
        bool v = ((unsigned)yy < 96u) && ((unsigned)xx < 96u);
        fsw[pi2][j]  = v ? g_f[((size_t)(n * 4 + br) * 9 + k) * HW + pg] : 0.f;
        pofs[pi2][j] = (((br + 1) * 2 + n) * HW + (v ? (yy * 96 + xx) : 0)) * 256;
    }
    __syncthreads();

    float4 b4 = *(const float4*)(bias + c);
    float4 z4 = *(const float4*)(g_z + ((size_t)n * HW + p) * 256 + c);
    float a0 = z4.x + b4.x, a1 = z4.y + b4.y, a2 = z4.z + b4.z, a3 = z4.w + b4.w;

#pragma unroll 4
    for (int j = 0; j < 36; j++) {
        float f = fsw[pi][j];
        const float* zp = g_z + (size_t)pofs[pi][j] + c;
        float4 v = *(const float4*)zp;
        a0 = fmaf(f, v.x, a0); a1 = fmaf(f, v.y, a1);
        a2 = fmaf(f, v.z, a2); a3 = fmaf(f, v.w, a3);
    }
    *(float4*)(g_y + ((size_t)n * HW + p) * 256 + c) = make_float4(a0, a1, a2, a3);

    float s = a0 + a1 + a2 + a3;
    float q = a0 * a0 + a1 * a1 + a2 * a2 + a3 * a3;
    s += __shfl_xor_sync(0xffffffffu, s, 1);
    q += __shfl_xor_sync(0xffffffffu, q, 1);
    if ((lane & 1) == 0) { bp_s[warp][lane >> 1] = s; bp_q[warp][lane >> 1] = q; }
    __syncthreads();
    if (tid < 64) {
        int g = tid >> 1, isq = tid & 1;
        int hf = g >> 4, gi = g & 15;
        float acc = 0.f;
#pragma unroll
        for (int pi2 = 0; pi2 < 8; pi2++)
            acc += isq ? bp_q[pi2 * 2 + hf][gi] : bp_s[pi2 * 2 + hf][gi];
        g_bpart[((size_t)n * 1152 + blockIdx.x) * 64 + tid] = acc;
    }
}

// ---------------- 5) GN stats ----------------
__global__ void __launch_bounds__(128) stats_kernel()
{
    int b = blockIdx.x;
    int n = b >> 5, g = b & 31;
    int tid = threadIdx.x;
    float s = 0.f, q = 0.f;
    for (int i = tid; i < 1152; i += 128) {
        size_t base = ((size_t)n * 1152 + i) * 64 + g * 2;
        s += g_bpart[base];
        q += g_bpart[base + 1];
    }
    __shared__ float ss[128], sq[128];
    ss[tid] = s; sq[tid] = q;
    __syncthreads();
    for (int off = 64; off > 0; off >>= 1) {
        if (tid < off) { ss[tid] += ss[tid + off]; sq[tid] += sq[tid + off]; }
        __syncthreads();
    }
    if (tid == 0) {
        const float invN = 1.f / 73728.f;
        float mean = ss[0] * invN;
        float var  = sq[0] * invN - mean * mean;
        g_stats[b * 2]     = mean;
        g_stats[b * 2 + 1] = rsqrtf(var + 1e-5f);
    }
}

// ---------------- 6) transpose + GN affine + relu ----------------
__global__ void __launch_bounds__(256) normT_kernel(
    const float* __restrict__ gamma, const float* __restrict__ beta,
    float* __restrict__ out)
{
    __shared__ float t[32][33];
    int p0 = blockIdx.x * 32, c0 = blockIdx.y * 32, n = blockIdx.z;
    int tx = threadIdx.x, ty = threadIdx.y;
#pragma unroll
    for (int r = 0; r < 4; r++)
        t[ty + 8 * r][tx] = g_y[((size_t)n * HW + p0 + ty + 8 * r) * 256 + c0 + tx];
    __syncthreads();
#pragma unroll
    for (int r = 0; r < 4; r++) {
        int c = c0 + ty + 8 * r, p = p0 + tx;
        int g = c >> 3;
        float mean = g_stats[(n * 32 + g) * 2];
        float rstd = g_stats[(n * 32 + g) * 2 + 1];
        float ga = gamma[c] * rstd;
        float be = beta[c] - mean * ga;
        float v = t[tx][ty + 8 * r];
        out[((size_t)n * 256 + c) * HW + p] = fmaxf(fmaf(v, ga, be), 0.f);
    }
}

// ---------------- launch ----------------
extern "C" void kernel_launch(void* const* d_in, const int* in_sizes, int n_in,
                              void* d_out, int out_size)
{
    const float* x     = (const float*)d_in[0];
    const float* wa    = (const float*)d_in[1];
    const float* wb    = (const float*)d_in[2];
    const float* wc    = (const float*)d_in[3];
    const float* wd    = (const float*)d_in[4];
    const float* wproj = (const float*)d_in[5];
    const float* bproj = (const float*)d_in[6];
    const float* gamma = (const float*)d_in[7];
    const float* beta  = (const float*)d_in[8];
    float* out = (float*)d_out;

    cudaFuncSetAttribute(gemm_mma_kernel, cudaFuncAttributeMaxDynamicSharedMemorySize, 73728);
    cudaFuncSetAttribute(gemm_u_kernel,   cudaFuncAttributeMaxDynamicSharedMemorySize, 73728);

    wsplit_kernel<<<1280, 256>>>(wproj);
    wl2split_kernel<<<384, 256>>>(wa, wb, wc, wd);
    xsplit_kernel<<<dim3(288, 8, 2), dim3(32, 8)>>>(x);
    gemm_u_kernel<<<dim3(72, 6, 2), 256, 73728>>>();
    gathersoftmax_kernel<<<288, 256>>>();
    gemm_mma_kernel<<<dim3(72, 4, 10), 256, 73728>>>();
    combine_kernel<<<dim3(1152, 2), 512>>>(bproj);
    stats_kernel<<<64, 128>>>();
    normT_kernel<<<dim3(288, 8, 2), dim3(32, 8)>>>(gamma, beta, out);
}

// round 11
// speedup vs baseline: 1.2026x; 1.1959x over previous
#include <cuda_runtime.h>
#include <cuda_fp16.h>
#include <cstdint>
#include <math.h>

#define HW    9216
#define CH    256
#define NB    2

// ---------------- scratch ----------------
__device__ float g_f[8ull * 9 * HW];               // [nb][o][HW] softmax tap weights
__device__ float g_u[(size_t)NB * 384 * HW];       // [n][br*96 + o*9+tap][HW]
__device__ float g_z[10ull * HW * CH + 400000];    // [b*2+n][p][c]
__device__ float g_y[(size_t)NB * HW * CH];        // [n][p][c]
__device__ float g_bpart[NB * 1152 * 64];
__device__ float g_stats[NB * 32 * 2];
__device__ __half g_w[5ull * 256 * 512];           // [b][m][k'=512: per 32-grp hi|lo]
__device__ __half g_xT[(size_t)NB * HW * 256];     // [n][p][c] fp16(x) only
__device__ __half g_wl2[384ull * 512];             // [m][k']

// ---------------- helpers ----------------
__device__ __forceinline__ uint32_t smem_u32(const void* p) {
    uint32_t a;
    asm("{ .reg .u64 t; cvta.to.shared.u64 t, %1; cvt.u32.u64 %0, t; }" : "=r"(a) : "l"(p));
    return a;
}
__device__ __forceinline__ void ldmatrix_x4(uint32_t& r0, uint32_t& r1, uint32_t& r2, uint32_t& r3, uint32_t addr) {
    asm volatile("ldmatrix.sync.aligned.m8n8.x4.shared.b16 {%0,%1,%2,%3}, [%4];"
        : "=r"(r0), "=r"(r1), "=r"(r2), "=r"(r3) : "r"(addr));
}
__device__ __forceinline__ void mma_f16(float* c, const uint32_t* a, uint32_t b0, uint32_t b1) {
    asm volatile("mma.sync.aligned.m16n8k16.row.col.f32.f16.f16.f32 "
        "{%0,%1,%2,%3}, {%4,%5,%6,%7}, {%8,%9}, {%0,%1,%2,%3};"
        : "+f"(c[0]), "+f"(c[1]), "+f"(c[2]), "+f"(c[3])
        : "r"(a[0]), "r"(a[1]), "r"(a[2]), "r"(a[3]), "r"(b0), "r"(b1));
}
__device__ __forceinline__ void cp_async16(uint32_t saddr, const void* gaddr) {
    asm volatile("cp.async.cg.shared.global [%0], [%1], 16;" :: "r"(saddr), "l"(gaddr));
}
// k' mapping: channel c, sel -> (c>>5)*64 + sel*32 + (c&31)
__device__ __forceinline__ int kprime(int c, int sel) {
    return ((c >> 5) << 6) + sel * 32 + (c & 31);
}

// ---------------- prep: split W (proj), interleaved hi/lo fp16 ----------------
__global__ void __launch_bounds__(256) wsplit_kernel(const float* __restrict__ wproj)
{
    int idx = blockIdx.x * 256 + threadIdx.x;
    if (idx >= 5 * 65536) return;
    int b = idx >> 16, rem = idx & 65535;
    int m = rem >> 8, c = rem & 255;
    float w = wproj[m * 1280 + b * 256 + c];
    __half hi = __float2half(w);
    __half lo = __float2half(w - __half2float(hi));
    size_t base = ((size_t)b * 256 + m) * 512;
    g_w[base + kprime(c, 0)] = hi;
    g_w[base + kprime(c, 1)] = lo;
}

// ---------------- prep: logits weights -> A[384][512] fp16 ----------------
__global__ void __launch_bounds__(256) wl2split_kernel(
    const float* __restrict__ wa, const float* __restrict__ wb,
    const float* __restrict__ wc, const float* __restrict__ wd)
{
    int idx = blockIdx.x * 256 + threadIdx.x;       // 384*256
    if (idx >= 98304) return;
    int c = idx & 255, m = idx >> 8;
    int br = m / 96, row = m - br * 96;
    float w = 0.f;
    if (row < 81) {
        int o = row / 9, tap = row - o * 9;
        const float* wp = (br == 0) ? wa : (br == 1) ? wb : (br == 2) ? wc : wd;
        w = wp[(o * 256 + c) * 9 + tap];
    }
    __half hi = __float2half(w);
    __half lo = __float2half(w - __half2float(hi));
    size_t base = (size_t)m * 512;
    g_wl2[base + kprime(c, 0)] = hi;
    g_wl2[base + kprime(c, 1)] = lo;
}

// ---------------- prep: transpose x to [p][c] fp16 ----------------
__global__ void __launch_bounds__(256) xsplit_kernel(const float* __restrict__ x)
{
    __shared__ float t[32][33];
    int p0 = blockIdx.x * 32, k0 = blockIdx.y * 32, n = blockIdx.z;
    int tx = threadIdx.x, ty = threadIdx.y;
#pragma unroll
    for (int r = 0; r < 4; r++)
        t[ty + 8 * r][tx] = x[((size_t)(n * 256 + k0 + ty + 8 * r)) * HW + p0 + tx];
    __syncthreads();
#pragma unroll
    for (int r = 0; r < 4; r++) {
        int p = p0 + ty + 8 * r, c = k0 + tx;
        g_xT[((size_t)n * HW + p) * 256 + c] = __float2half(t[tx][ty + 8 * r]);
    }
}

// ================= GEMM tile: 128m x 128p; 8 chunks of 32 channels =========
// A smem: 128 rows x 128B ([32 hi | 32 lo] per chunk col), 16KB
// B smem: 128 rows x 128B (only u0..3 = 32 ch fp16 valid), 16KB
// stage 32KB, 3 stages = 96KB (2 CTA/SM). warps: warp_m = wid&1 (64m), warp_n = wid>>1 (32p)
struct MmaCtx {
    uint32_t sbase;
    int tid, lane, warp_m, warp_n;
    float acc[4][4][4];
    __device__ __forceinline__ void init(uint32_t sb, int t) {
        sbase = sb; tid = t; lane = t & 31;
        int wid = t >> 5;
        warp_m = wid & 1; warp_n = wid >> 1;
#pragma unroll
        for (int i = 0; i < 4; i++)
#pragma unroll
            for (int j = 0; j < 4; j++)
#pragma unroll
                for (int r = 0; r < 4; r++) acc[i][j][r] = 0.f;
    }
    __device__ __forceinline__ void fill(int buf, const char* Ag, const char* Bg) {
        uint32_t aOff = buf * 32768u;
        uint32_t bOff = 16384u + buf * 32768u;
#pragma unroll
        for (int r = 0; r < 4; r++) {               // A: 1024 16B units
            int idx = tid + 256 * r;
            int row = idx >> 3, u = idx & 7;
            uint32_t sw = row * 128 + ((u ^ (row & 7)) << 4);
            cp_async16(sbase + aOff + sw, Ag + (size_t)row * 1024 + u * 16);
        }
#pragma unroll
        for (int r = 0; r < 2; r++) {               // B: 512 16B units (u0..3)
            int idx = tid + 256 * r;
            int row = idx >> 2, u = idx & 3;
            uint32_t sw = row * 128 + ((u ^ (row & 7)) << 4);
            cp_async16(sbase + bOff + sw, Bg + (size_t)row * 512 + u * 16);
        }
        asm volatile("cp.async.commit_group;");
    }
    __device__ __forceinline__ void compute(int buf) {
        uint32_t aB = sbase + buf * 32768u;
        uint32_t bB = sbase + 16384u + buf * 32768u;
#pragma unroll
        for (int ks = 0; ks < 2; ks++) {
            int u0 = ks * 2 + (lane >> 4);          // 0..3
            int u0l = u0 + 4;                       // lo half of A row
            uint32_t a[4][4], bb[2][4];
#pragma unroll
            for (int q = 0; q < 2; q++) {
                int row = warp_n * 32 + q * 16 + (lane & 15);
                ldmatrix_x4(bb[q][0], bb[q][1], bb[q][2], bb[q][3],
                            bB + row * 128 + (((unsigned)(u0 ^ (row & 7))) << 4));
            }
#pragma unroll
            for (int mi = 0; mi < 4; mi++) {        // A hi
                int row = warp_m * 64 + mi * 16 + (lane & 15);
                ldmatrix_x4(a[mi][0], a[mi][1], a[mi][2], a[mi][3],
                            aB + row * 128 + (((unsigned)(u0 ^ (row & 7))) << 4));
            }
#pragma unroll
            for (int mi = 0; mi < 4; mi++)
#pragma unroll
                for (int nj = 0; nj < 4; nj++) {
                    int q = nj >> 1, pr = nj & 1;
                    mma_f16(acc[mi][nj], a[mi], bb[q][pr], bb[q][pr + 2]);
                }
#pragma unroll
            for (int mi = 0; mi < 4; mi++) {        // A lo
                int row = warp_m * 64 + mi * 16 + (lane & 15);
                ldmatrix_x4(a[mi][0], a[mi][1], a[mi][2], a[mi][3],
                            aB + row * 128 + (((unsigned)(u0l ^ (row & 7))) << 4));
            }
#pragma unroll
            for (int mi = 0; mi < 4; mi++)
#pragma unroll
                for (int nj = 0; nj < 4; nj++) {
                    int q = nj >> 1, pr = nj & 1;
                    mma_f16(acc[mi][nj], a[mi], bb[q][pr], bb[q][pr + 2]);
                }
        }
    }
    __device__ __forceinline__ void run(const char* Abase, const char* Bbase) {
        fill(0, Abase, Bbase);
        fill(1, Abase + 128, Bbase + 64);
        for (int i = 0; i < 8; i++) {
            if (i < 6) asm volatile("cp.async.wait_group 1;");
            else       asm volatile("cp.async.wait_group 0;");
            __syncthreads();
            compute(i % 3);
            if (i + 2 < 8) fill((i + 2) % 3, Abase + (i + 2) * 128, Bbase + (i + 2) * 64);
        }
        __syncthreads();
    }
    __device__ __forceinline__ void stage_out(float* stage) {
#pragma unroll
        for (int mi = 0; mi < 4; mi++)
#pragma unroll
            for (int nj = 0; nj < 4; nj++)
#pragma unroll
                for (int r = 0; r < 4; r++) {
                    int p = warp_n * 32 + nj * 8 + 2 * (lane & 3) + (r & 1);
                    int m = warp_m * 64 + mi * 16 + (lane >> 2) + ((r >> 1) << 3);
                    stage[p * 132 + m] = acc[mi][nj][r];
                }
    }
};

// ---------------- 1) U-GEMM: grid (72, 3, 2) ----------------
__global__ void __launch_bounds__(256, 2) gemm_u_kernel()
{
    extern __shared__ char dsm[];
    MmaCtx g;
    g.init(smem_u32(dsm), threadIdx.x);
    int pbase = blockIdx.x * 128;
    int mbase = blockIdx.y * 128;
    int n = blockIdx.z;

    g.run((const char*)g_wl2 + (size_t)mbase * 1024,
          (const char*)g_xT + ((size_t)n * HW + pbase) * 512);

    float* stage = (float*)dsm;
    g.stage_out(stage);
    __syncthreads();
#pragma unroll
    for (int rr = 0; rr < 16; rr++) {
        int idx = threadIdx.x + 256 * rr;
        int m = idx >> 5, p4 = (idx & 31) * 4;
        float4 v = make_float4(stage[p4 * 132 + m], stage[(p4 + 1) * 132 + m],
                               stage[(p4 + 2) * 132 + m], stage[(p4 + 3) * 132 + m]);
        *(float4*)(g_u + ((size_t)n * 384 + mbase + m) * HW + pbase + p4) = v;
    }
}

// ---------------- 2) gather taps + softmax ----------------
__global__ void __launch_bounds__(256) gathersoftmax_kernel()
{
    int id = blockIdx.x * 256 + threadIdx.x;
    int p = id % HW;
    int nb = id / HW;
    int n = nb >> 2, br = nb & 3;
    int d = (br == 0) ? 1 : (br == 1) ? 4 : (br == 2) ? 8 : 12;
    int y = p / 96, x = p - y * 96;

    int po[9];
#pragma unroll
    for (int t = 0; t < 9; t++) {
        int yy = y + (t / 3 - 1) * d;
        int xx = x + (t % 3 - 1) * d;
        po[t] = (((unsigned)yy < 96u) && ((unsigned)xx < 96u)) ? (yy * 96 + xx) : -1;
    }

    const float* ub = g_u + ((size_t)n * 384 + br * 96) * HW;
    float l[9];
#pragma unroll
    for (int o = 0; o < 9; o++) {
        float s = 0.f;
#pragma unroll
        for (int t = 0; t < 9; t++)
            if (po[t] >= 0) s += ub[(size_t)(o * 9 + t) * HW + po[t]];
        l[o] = s;
    }
    float m = l[0];
#pragma unroll
    for (int o = 1; o < 9; o++) m = fmaxf(m, l[o]);
    float s = 0.f;
#pragma unroll
    for (int o = 0; o < 9; o++) { l[o] = expf(l[o] - m); s += l[o]; }
    float inv = 1.f / s;
#pragma unroll
    for (int o = 0; o < 9; o++)
        g_f[((size_t)nb * 9 + o) * HW + p] = l[o] * inv;
}

// ---------------- 3) proj GEMM: grid (72, 2, 10) ----------------
__global__ void __launch_bounds__(256, 2) gemm_mma_kernel()
{
    extern __shared__ char dsm[];
    MmaCtx g;
    g.init(smem_u32(dsm), threadIdx.x);
    int pbase = blockIdx.x * 128;
    int mbase = blockIdx.y * 128;
    int bn = blockIdx.z;
    int b = bn >> 1, n = bn & 1;

    g.run((const char*)g_w + ((size_t)b * 256 + mbase) * 1024,
          (const char*)g_xT + ((size_t)n * HW + pbase) * 512);

    float* stage = (float*)dsm;
    g.stage_out(stage);
    __syncthreads();
    float* zo = (float*)g_z + ((size_t)bn * HW + pbase) * 256 + mbase;
#pragma unroll
    for (int r = 0; r < 16; r++) {
        int idx = threadIdx.x + 256 * r;
        int px = idx >> 5, c4 = (idx & 31) * 4;
        float4 v = *(float4*)&stage[px * 132 + c4];
        *(float4*)(zo + (size_t)px * 256 + c4) = v;
    }
}

// ---------------- 4) combine ----------------
__global__ void __launch_bounds__(512) combine_kernel(const float* __restrict__ bias)
{
    int tid = threadIdx.x;
    int n = blockIdx.y;
    int p0 = blockIdx.x * 8;
    int warp = tid >> 5, lane = tid & 31;
    int pi = warp >> 1, half = warp & 1;
    int p = p0 + pi;
    int c = half * 128 + lane * 4;

    __shared__ float fsw[8][40];
    __shared__ int   pofs[8][40];
    __shared__ float bp_s[16][16];
    __shared__ float bp_q[16][16];

    if (tid < 288) {
        int pi2 = tid / 36, j = tid - pi2 * 36;
        int br = j / 9, k = j - br * 9;
        int d = (br == 0) ? 1 : (br == 1) ? 4 : (br == 2) ? 8 : 12;
        int pg = p0 + pi2;
        int yy = pg / 96 + (k / 3 - 1) * d;
        int xx = pg % 96 + (k % 3 - 1) * d;
        bool v = ((unsigned)yy < 96u) && ((unsigned)xx < 96u);
        fsw[pi2][j]  = v ? g_f[((size_t)(n * 4 + br) * 9 + k) * HW + pg] : 0.f;
        pofs[pi2][j] = (((br + 1) * 2 + n) * HW + (v ? (yy * 96 + xx) : 0)) * 256;
    }
    __syncthreads();

    float4 b4 = *(const float4*)(bias + c);
    float4 z4 = *(const float4*)(g_z + ((size_t)n * HW + p) * 256 + c);
    float a0 = z4.x + b4.x, a1 = z4.y + b4.y, a2 = z4.z + b4.z, a3 = z4.w + b4.w;

#pragma unroll 4
    for (int j = 0; j < 36; j++) {
        float f = fsw[pi][j];
        const float* zp = g_z + (size_t)pofs[pi][j] + c;
        float4 v = *(const float4*)zp;
        a0 = fmaf(f, v.x, a0); a1 = fmaf(f, v.y, a1);
        a2 = fmaf(f, v.z, a2); a3 = fmaf(f, v.w, a3);
    }
    *(float4*)(g_y + ((size_t)n * HW + p) * 256 + c) = make_float4(a0, a1, a2, a3);

    float s = a0 + a1 + a2 + a3;
    float q = a0 * a0 + a1 * a1 + a2 * a2 + a3 * a3;
    s += __shfl_xor_sync(0xffffffffu, s, 1);
    q += __shfl_xor_sync(0xffffffffu, q, 1);
    if ((lane & 1) == 0) { bp_s[warp][lane >> 1] = s; bp_q[warp][lane >> 1] = q; }
    __syncthreads();
    if (tid < 64) {
        int g = tid >> 1, isq = tid & 1;
        int hf = g >> 4, gi = g & 15;
        float acc = 0.f;
#pragma unroll
        for (int pi2 = 0; pi2 < 8; pi2++)
            acc += isq ? bp_q[pi2 * 2 + hf][gi] : bp_s[pi2 * 2 + hf][gi];
        g_bpart[((size_t)n * 1152 + blockIdx.x) * 64 + tid] = acc;
    }
}

// ---------------- 5) GN stats ----------------
__global__ void __launch_bounds__(128) stats_kernel()
{
    int b = blockIdx.x;
    int n = b >> 5, g = b & 31;
    int tid = threadIdx.x;
    float s = 0.f, q = 0.f;
    for (int i = tid; i < 1152; i += 128) {
        size_t base = ((size_t)n * 1152 + i) * 64 + g * 2;
        s += g_bpart[base];
        q += g_bpart[base + 1];
    }
    __shared__ float ss[128], sq[128];
    ss[tid] = s; sq[tid] = q;
    __syncthreads();
    for (int off = 64; off > 0; off >>= 1) {
        if (tid < off) { ss[tid] += ss[tid + off]; sq[tid] += sq[tid + off]; }
        __syncthreads();
    }
    if (tid == 0) {
        const float invN = 1.f / 73728.f;
        float mean = ss[0] * invN;
        float var  = sq[0] * invN - mean * mean;
        g_stats[b * 2]     = mean;
        g_stats[b * 2 + 1] = rsqrtf(var + 1e-5f);
    }
}

// ---------------- 6) transpose + GN affine + relu ----------------
__global__ void __launch_bounds__(256) normT_kernel(
    const float* __restrict__ gamma, const float* __restrict__ beta,
    float* __restrict__ out)
{
    __shared__ float t[32][33];
    int p0 = blockIdx.x * 32, c0 = blockIdx.y * 32, n = blockIdx.z;
    int tx = threadIdx.x, ty = threadIdx.y;
#pragma unroll
    for (int r = 0; r < 4; r++)
        t[ty + 8 * r][tx] = g_y[((size_t)n * HW + p0 + ty + 8 * r) * 256 + c0 + tx];
    __syncthreads();
#pragma unroll
    for (int r = 0; r < 4; r++) {
        int c = c0 + ty + 8 * r, p = p0 + tx;
        int g = c >> 3;
        float mean = g_stats[(n * 32 + g) * 2];
        float rstd = g_stats[(n * 32 + g) * 2 + 1];
        float ga = gamma[c] * rstd;
        float be = beta[c] - mean * ga;
        float v = t[tx][ty + 8 * r];
        out[((size_t)n * 256 + c) * HW + p] = fmaxf(fmaf(v, ga, be), 0.f);
    }
}

// ---------------- launch ----------------
extern "C" void kernel_launch(void* const* d_in, const int* in_sizes, int n_in,
                              void* d_out, int out_size)
{
    const float* x     = (const float*)d_in[0];
    const float* wa    = (const float*)d_in[1];
    const float* wb    = (const float*)d_in[2];
    const float* wc    = (const float*)d_in[3];
    const float* wd    = (const float*)d_in[4];
    const float* wproj = (const float*)d_in[5];
    const float* bproj = (const float*)d_in[6];
    const float* gamma = (const float*)d_in[7];
    const float* beta  = (const float*)d_in[8];
    float* out = (float*)d_out;

    cudaFuncSetAttribute(gemm_mma_kernel, cudaFuncAttributeMaxDynamicSharedMemorySize, 98304);
    cudaFuncSetAttribute(gemm_u_kernel,   cudaFuncAttributeMaxDynamicSharedMemorySize, 98304);

    wsplit_kernel<<<1280, 256>>>(wproj);
    wl2split_kernel<<<384, 256>>>(wa, wb, wc, wd);
    xsplit_kernel<<<dim3(288, 8, 2), dim3(32, 8)>>>(x);
    gemm_u_kernel<<<dim3(72, 3, 2), 256, 98304>>>();
    gathersoftmax_kernel<<<288, 256>>>();
    gemm_mma_kernel<<<dim3(72, 2, 10), 256, 98304>>>();
    combine_kernel<<<dim3(1152, 2), 512>>>(bproj);
    stats_kernel<<<64, 128>>>();
    normT_kernel<<<dim3(288, 8, 2), dim3(32, 8)>>>(gamma, beta, out);
}

// round 12
// speedup vs baseline: 1.5353x; 1.2766x over previous
#include <cuda_runtime.h>
#include <cuda_fp16.h>
#include <cstdint>
#include <math.h>

#define HW    9216
#define CH    256
#define NB    2

// ---------------- scratch ----------------
__device__ float g_f[8ull * 9 * HW];               // [nb][o][HW] softmax tap weights
__device__ float g_u[(size_t)NB * 384 * HW];       // [n][br*96 + o*9+tap][HW]
__device__ float g_z[10ull * HW * CH + 400000];    // [b*2+n][p][c]
__device__ float g_y[(size_t)NB * HW * CH];        // [n][p][c]
__device__ float g_bpart[NB * 1152 * 64];
__device__ float g_stats[NB * 32 * 2];
__device__ __half g_w[5ull * 256 * 256];           // [b][m][c] fp16(w)
__device__ __half g_xT[(size_t)NB * HW * 256];     // [n][p][c] fp16(x)
__device__ __half g_wl2[384ull * 256];             // [m][c] fp16 logits weights

// ---------------- helpers ----------------
__device__ __forceinline__ uint32_t smem_u32(const void* p) {
    uint32_t a;
    asm("{ .reg .u64 t; cvta.to.shared.u64 t, %1; cvt.u32.u64 %0, t; }" : "=r"(a) : "l"(p));
    return a;
}
__device__ __forceinline__ void ldmatrix_x4(uint32_t& r0, uint32_t& r1, uint32_t& r2, uint32_t& r3, uint32_t addr) {
    asm volatile("ldmatrix.sync.aligned.m8n8.x4.shared.b16 {%0,%1,%2,%3}, [%4];"
        : "=r"(r0), "=r"(r1), "=r"(r2), "=r"(r3) : "r"(addr));
}
__device__ __forceinline__ void mma_f16(float* c, const uint32_t* a, uint32_t b0, uint32_t b1) {
    asm volatile("mma.sync.aligned.m16n8k16.row.col.f32.f16.f16.f32 "
        "{%0,%1,%2,%3}, {%4,%5,%6,%7}, {%8,%9}, {%0,%1,%2,%3};"
        : "+f"(c[0]), "+f"(c[1]), "+f"(c[2]), "+f"(c[3])
        : "r"(a[0]), "r"(a[1]), "r"(a[2]), "r"(a[3]), "r"(b0), "r"(b1));
}
__device__ __forceinline__ void cp_async16(uint32_t saddr, const void* gaddr) {
    asm volatile("cp.async.cg.shared.global [%0], [%1], 16;" :: "r"(saddr), "l"(gaddr));
}

// ---------------- prep: W (proj) -> fp16 ----------------
__global__ void __launch_bounds__(256) wsplit_kernel(const float* __restrict__ wproj)
{
    int idx = blockIdx.x * 256 + threadIdx.x;
    if (idx >= 5 * 65536) return;
    int b = idx >> 16, rem = idx & 65535;
    int m = rem >> 8, c = rem & 255;
    g_w[((size_t)b * 256 + m) * 256 + c] = __float2half(wproj[m * 1280 + b * 256 + c]);
}

// ---------------- prep: logits weights -> A[384][256] fp16 ----------------
__global__ void __launch_bounds__(256) wl2split_kernel(
    const float* __restrict__ wa, const float* __restrict__ wb,
    const float* __restrict__ wc, const float* __restrict__ wd)
{
    int idx = blockIdx.x * 256 + threadIdx.x;       // 384*256
    if (idx >= 98304) return;
    int c = idx & 255, m = idx >> 8;
    int br = m / 96, row = m - br * 96;
    float w = 0.f;
    if (row < 81) {
        int o = row / 9, tap = row - o * 9;
        const float* wp = (br == 0) ? wa : (br == 1) ? wb : (br == 2) ? wc : wd;
        w = wp[(o * 256 + c) * 9 + tap];
    }
    g_wl2[(size_t)m * 256 + c] = __float2half(w);
}

// ---------------- prep: transpose x to [p][c] fp16 ----------------
__global__ void __launch_bounds__(256) xsplit_kernel(const float* __restrict__ x)
{
    __shared__ float t[32][33];
    int p0 = blockIdx.x * 32, k0 = blockIdx.y * 32, n = blockIdx.z;
    int tx = threadIdx.x, ty = threadIdx.y;
#pragma unroll
    for (int r = 0; r < 4; r++)
        t[ty + 8 * r][tx] = x[((size_t)(n * 256 + k0 + ty + 8 * r)) * HW + p0 + tx];
    __syncthreads();
#pragma unroll
    for (int r = 0; r < 4; r++) {
        int p = p0 + ty + 8 * r, c = k0 + tx;
        g_xT[((size_t)n * HW + p) * 256 + c] = __float2half(t[tx][ty + 8 * r]);
    }
}

// ================= GEMM tile: 128m x 128p; K=256 in 4 chunks of 64 ==========
// A smem: 128 rows x 128B (64 ch fp16), B same; stage 32KB, 3 stages = 96KB (2 CTA/SM)
// warps 8: warp_m = wid&1 (64m), warp_n = wid>>1 (32p)
struct MmaCtx {
    uint32_t sbase;
    int tid, lane, warp_m, warp_n;
    float acc[4][4][4];
    __device__ __forceinline__ void init(uint32_t sb, int t) {
        sbase = sb; tid = t; lane = t & 31;
        int wid = t >> 5;
        warp_m = wid & 1; warp_n = wid >> 1;
#pragma unroll
        for (int i = 0; i < 4; i++)
#pragma unroll
            for (int j = 0; j < 4; j++)
#pragma unroll
                for (int r = 0; r < 4; r++) acc[i][j][r] = 0.f;
    }
    // A,B: row stride 512 bytes, chunk offset = kc*128 bytes
    __device__ __forceinline__ void fill(int buf, const char* Ag, const char* Bg) {
        uint32_t aOff = buf * 32768u;
        uint32_t bOff = 16384u + buf * 32768u;
#pragma unroll
        for (int r = 0; r < 4; r++) {
            int idx = tid + 256 * r;          // 0..1023 : row(128) x u(8)
            int row = idx >> 3, u = idx & 7;
            uint32_t sw = row * 128 + ((u ^ (row & 7)) << 4);
            cp_async16(sbase + aOff + sw, Ag + (size_t)row * 512 + u * 16);
            cp_async16(sbase + bOff + sw, Bg + (size_t)row * 512 + u * 16);
        }
        asm volatile("cp.async.commit_group;");
    }
    __device__ __forceinline__ void compute(int buf) {
        uint32_t aB = sbase + buf * 32768u;
        uint32_t bB = sbase + 16384u + buf * 32768u;
#pragma unroll
        for (int ks = 0; ks < 4; ks++) {
            int u0 = ks * 2 + (lane >> 4);
            uint32_t a[4][4], bb[2][4];
#pragma unroll
            for (int q = 0; q < 2; q++) {
                int row = warp_n * 32 + q * 16 + (lane & 15);
                ldmatrix_x4(bb[q][0], bb[q][1], bb[q][2], bb[q][3],
                            bB + row * 128 + (((unsigned)(u0 ^ (row & 7))) << 4));
            }
#pragma unroll
            for (int mi = 0; mi < 4; mi++) {
                int row = warp_m * 64 + mi * 16 + (lane & 15);
                ldmatrix_x4(a[mi][0], a[mi][1], a[mi][2], a[mi][3],
                            aB + row * 128 + (((unsigned)(u0 ^ (row & 7))) << 4));
            }
#pragma unroll
            for (int mi = 0; mi < 4; mi++)
#pragma unroll
                for (int nj = 0; nj < 4; nj++) {
                    int q = nj >> 1, pr = nj & 1;
                    mma_f16(acc[mi][nj], a[mi], bb[q][pr], bb[q][pr + 2]);
                }
        }
    }
    __device__ __forceinline__ void run(const char* Abase, const char* Bbase) {
        fill(0, Abase, Bbase);
        fill(1, Abase + 128, Bbase + 128);
        for (int i = 0; i < 4; i++) {
            if (i < 3) asm volatile("cp.async.wait_group 1;");
            else       asm volatile("cp.async.wait_group 0;");
            __syncthreads();
            compute(i % 3);
            if (i + 2 < 4) fill((i + 2) % 3, Abase + (i + 2) * 128, Bbase + (i + 2) * 128);
        }
        __syncthreads();
    }
    __device__ __forceinline__ void stage_out(float* stage) {
#pragma unroll
        for (int mi = 0; mi < 4; mi++)
#pragma unroll
            for (int nj = 0; nj < 4; nj++)
#pragma unroll
                for (int r = 0; r < 4; r++) {
                    int p = warp_n * 32 + nj * 8 + 2 * (lane & 3) + (r & 1);
                    int m = warp_m * 64 + mi * 16 + (lane >> 2) + ((r >> 1) << 3);
                    stage[p * 132 + m] = acc[mi][nj][r];
                }
    }
};

// ---------------- 1) U-GEMM: grid (72, 3, 2) ----------------
__global__ void __launch_bounds__(256, 2) gemm_u_kernel()
{
    extern __shared__ char dsm[];
    MmaCtx g;
    g.init(smem_u32(dsm), threadIdx.x);
    int pbase = blockIdx.x * 128;
    int mbase = blockIdx.y * 128;
    int n = blockIdx.z;

    g.run((const char*)g_wl2 + (size_t)mbase * 512,
          (const char*)g_xT + ((size_t)n * HW + pbase) * 512);

    float* stage = (float*)dsm;
    g.stage_out(stage);
    __syncthreads();
#pragma unroll
    for (int rr = 0; rr < 16; rr++) {
        int idx = threadIdx.x + 256 * rr;
        int m = idx >> 5, p4 = (idx & 31) * 4;
        float4 v = make_float4(stage[p4 * 132 + m], stage[(p4 + 1) * 132 + m],
                               stage[(p4 + 2) * 132 + m], stage[(p4 + 3) * 132 + m]);
        *(float4*)(g_u + ((size_t)n * 384 + mbase + m) * HW + pbase + p4) = v;
    }
}

// ---------------- 2) gather taps + softmax ----------------
__global__ void __launch_bounds__(256) gathersoftmax_kernel()
{
    int id = blockIdx.x * 256 + threadIdx.x;
    int p = id % HW;
    int nb = id / HW;
    int n = nb >> 2, br = nb & 3;
    int d = (br == 0) ? 1 : (br == 1) ? 4 : (br == 2) ? 8 : 12;
    int y = p / 96, x = p - y * 96;

    int po[9];
#pragma unroll
    for (int t = 0; t < 9; t++) {
        int yy = y + (t / 3 - 1) * d;
        int xx = x + (t % 3 - 1) * d;
        po[t] = (((unsigned)yy < 96u) && ((unsigned)xx < 96u)) ? (yy * 96 + xx) : -1;
    }

    const float* ub = g_u + ((size_t)n * 384 + br * 96) * HW;
    float l[9];
#pragma unroll
    for (int o = 0; o < 9; o++) {
        float s = 0.f;
#pragma unroll
        for (int t = 0; t < 9; t++)
            if (po[t] >= 0) s += ub[(size_t)(o * 9 + t) * HW + po[t]];
        l[o] = s;
    }
    float m = l[0];
#pragma unroll
    for (int o = 1; o < 9; o++) m = fmaxf(m, l[o]);
    float s = 0.f;
#pragma unroll
    for (int o = 0; o < 9; o++) { l[o] = expf(l[o] - m); s += l[o]; }
    float inv = 1.f / s;
#pragma unroll
    for (int o = 0; o < 9; o++)
        g_f[((size_t)nb * 9 + o) * HW + p] = l[o] * inv;
}

// ---------------- 3) proj GEMM: grid (72, 2, 10) ----------------
__global__ void __launch_bounds__(256, 2) gemm_mma_kernel()
{
    extern __shared__ char dsm[];
    MmaCtx g;
    g.init(smem_u32(dsm), threadIdx.x);
    int pbase = blockIdx.x * 128;
    int mbase = blockIdx.y * 128;
    int bn = blockIdx.z;
    int b = bn >> 1, n = bn & 1;

    g.run((const char*)g_w + ((size_t)b * 256 + mbase) * 512,
          (const char*)g_xT + ((size_t)n * HW + pbase) * 512);

    float* stage = (float*)dsm;
    g.stage_out(stage);
    __syncthreads();
    float* zo = (float*)g_z + ((size_t)bn * HW + pbase) * 256 + mbase;
#pragma unroll
    for (int r = 0; r < 16; r++) {
        int idx = threadIdx.x + 256 * r;
        int px = idx >> 5, c4 = (idx & 31) * 4;
        float4 v = *(float4*)&stage[px * 132 + c4];
        *(float4*)(zo + (size_t)px * 256 + c4) = v;
    }
}

// ---------------- 4) combine ----------------
__global__ void __launch_bounds__(512) combine_kernel(const float* __restrict__ bias)
{
    int tid = threadIdx.x;
    int n = blockIdx.y;
    int p0 = blockIdx.x * 8;
    int warp = tid >> 5, lane = tid & 31;
    int pi = warp >> 1, half = warp & 1;
    int p = p0 + pi;
    int c = half * 128 + lane * 4;

    __shared__ float fsw[8][40];
    __shared__ int   pofs[8][40];
    __shared__ float bp_s[16][16];
    __shared__ float bp_q[16][16];

    if (tid < 288) {
        int pi2 = tid / 36, j = tid - pi2 * 36;
        int br = j / 9, k = j - br * 9;
        int d = (br == 0) ? 1 : (br == 1) ? 4 : (br == 2) ? 8 : 12;
        int pg = p0 + pi2;
        int yy = pg / 96 + (k / 3 - 1) * d;
        int xx = pg % 96 + (k % 3 - 1) * d;
        bool v = ((unsigned)yy < 96u) && ((unsigned)xx < 96u);
        fsw[pi2][j]  = v ? g_f[((size_t)(n * 4 + br) * 9 + k) * HW + pg] : 0.f;
        pofs[pi2][j] = (((br + 1) * 2 + n) * HW + (v ? (yy * 96 + xx) : 0)) * 256;
    }
    __syncthreads();

    float4 b4 = *(const float4*)(bias + c);
    float4 z4 = *(const float4*)(g_z + ((size_t)n * HW + p) * 256 + c);
    float a0 = z4.x + b4.x, a1 = z4.y + b4.y, a2 = z4.z + b4.z, a3 = z4.w + b4.w;

#pragma unroll 4
    for (int j = 0; j < 36; j++) {
        float f = fsw[pi][j];
        const float* zp = g_z + (size_t)pofs[pi][j] + c;
        float4 v = *(const float4*)zp;
        a0 = fmaf(f, v.x, a0); a1 = fmaf(f, v.y, a1);
        a2 = fmaf(f, v.z, a2); a3 = fmaf(f, v.w, a3);
    }
    *(float4*)(g_y + ((size_t)n * HW + p) * 256 + c) = make_float4(a0, a1, a2, a3);

    float s = a0 + a1 + a2 + a3;
    float q = a0 * a0 + a1 * a1 + a2 * a2 + a3 * a3;
    s += __shfl_xor_sync(0xffffffffu, s, 1);
    q += __shfl_xor_sync(0xffffffffu, q, 1);
    if ((lane & 1) == 0) { bp_s[warp][lane >> 1] = s; bp_q[warp][lane >> 1] = q; }
    __syncthreads();
    if (tid < 64) {
        int g = tid >> 1, isq = tid & 1;
        int hf = g >> 4, gi = g & 15;
        float acc = 0.f;
#pragma unroll
        for (int pi2 = 0; pi2 < 8; pi2++)
            acc += isq ? bp_q[pi2 * 2 + hf][gi] : bp_s[pi2 * 2 + hf][gi];
        g_bpart[((size_t)n * 1152 + blockIdx.x) * 64 + tid] = acc;
    }
}

// ---------------- 5) GN stats ----------------
__global__ void __launch_bounds__(128) stats_kernel()
{
    int b = blockIdx.x;
    int n = b >> 5, g = b & 31;
    int tid = threadIdx.x;
    float s = 0.f, q = 0.f;
    for (int i = tid; i < 1152; i += 128) {
        size_t base = ((size_t)n * 1152 + i) * 64 + g * 2;
        s += g_bpart[base];
        q += g_bpart[base + 1];
    }
    __shared__ float ss[128], sq[128];
    ss[tid] = s; sq[tid] = q;
    __syncthreads();
    for (int off = 64; off > 0; off >>= 1) {
        if (tid < off) { ss[tid] += ss[tid + off]; sq[tid] += sq[tid + off]; }
        __syncthreads();
    }
    if (tid == 0) {
        const float invN = 1.f / 73728.f;
        float mean = ss[0] * invN;
        float var  = sq[0] * invN - mean * mean;
        g_stats[b * 2]     = mean;
        g_stats[b * 2 + 1] = rsqrtf(var + 1e-5f);
    }
}

// ---------------- 6) transpose + GN affine + relu ----------------
__global__ void __launch_bounds__(256) normT_kernel(
    const float* __restrict__ gamma, const float* __restrict__ beta,
    float* __restrict__ out)
{
    __shared__ float t[32][33];
    int p0 = blockIdx.x * 32, c0 = blockIdx.y * 32, n = blockIdx.z;
    int tx = threadIdx.x, ty = threadIdx.y;
#pragma unroll
    for (int r = 0; r < 4; r++)
        t[ty + 8 * r][tx] = g_y[((size_t)n * HW + p0 + ty + 8 * r) * 256 + c0 + tx];
    __syncthreads();
#pragma unroll
    for (int r = 0; r < 4; r++) {
        int c = c0 + ty + 8 * r, p = p0 + tx;
        int g = c >> 3;
        float mean = g_stats[(n * 32 + g) * 2];
        float rstd = g_stats[(n * 32 + g) * 2 + 1];
        float ga = gamma[c] * rstd;
        float be = beta[c] - mean * ga;
        float v = t[tx][ty + 8 * r];
        out[((size_t)n * 256 + c) * HW + p] = fmaxf(fmaf(v, ga, be), 0.f);
    }
}

// ---------------- launch ----------------
extern "C" void kernel_launch(void* const* d_in, const int* in_sizes, int n_in,
                              void* d_out, int out_size)
{
    const float* x     = (const float*)d_in[0];
    const float* wa    = (const float*)d_in[1];
    const float* wb    = (const float*)d_in[2];
    const float* wc    = (const float*)d_in[3];
    const float* wd    = (const float*)d_in[4];
    const float* wproj = (const float*)d_in[5];
    const float* bproj = (const float*)d_in[6];
    const float* gamma = (const float*)d_in[7];
    const float* beta  = (const float*)d_in[8];
    float* out = (float*)d_out;

    cudaFuncSetAttribute(gemm_mma_kernel, cudaFuncAttributeMaxDynamicSharedMemorySize, 98304);
    cudaFuncSetAttribute(gemm_u_kernel,   cudaFuncAttributeMaxDynamicSharedMemorySize, 98304);

    wsplit_kernel<<<1280, 256>>>(wproj);
    wl2split_kernel<<<384, 256>>>(wa, wb, wc, wd);
    xsplit_kernel<<<dim3(288, 8, 2), dim3(32, 8)>>>(x);
    gemm_u_kernel<<<dim3(72, 3, 2), 256, 98304>>>();
    gathersoftmax_kernel<<<288, 256>>>();
    gemm_mma_kernel<<<dim3(72, 2, 10), 256, 98304>>>();
    combine_kernel<<<dim3(1152, 2), 512>>>(bproj);
    stats_kernel<<<64, 128>>>();
    normT_kernel<<<dim3(288, 8, 2), dim3(32, 8)>>>(gamma, beta, out);
}

// round 13
// speedup vs baseline: 1.8201x; 1.1855x over previous
#include <cuda_runtime.h>
#include <cuda_fp16.h>
#include <cstdint>
#include <math.h>

#define HW    9216
#define CH    256
#define NB    2

// ---------------- scratch ----------------
__device__ float g_f[8ull * 9 * HW];               // [nb][o][HW] softmax tap weights
__device__ float g_u[(size_t)NB * 384 * HW];       // [n][br*96 + o*9+tap][HW]
__device__ __half g_z[10ull * HW * CH + 400000];   // [b*2+n][p][c]  fp16
__device__ float g_y[(size_t)NB * HW * CH];        // [n][p][c]
__device__ float g_bpart[NB * 1152 * 64];
__device__ float g_stats[NB * 32 * 2];
__device__ __half g_w[5ull * 256 * 256];           // [b][m][c] fp16(w)
__device__ __half g_xT[(size_t)NB * HW * 256];     // [n][p][c] fp16(x)
__device__ __half g_wl2[384ull * 256];             // [m][c] fp16 logits weights

// ---------------- helpers ----------------
__device__ __forceinline__ uint32_t smem_u32(const void* p) {
    uint32_t a;
    asm("{ .reg .u64 t; cvta.to.shared.u64 t, %1; cvt.u32.u64 %0, t; }" : "=r"(a) : "l"(p));
    return a;
}
__device__ __forceinline__ void ldmatrix_x4(uint32_t& r0, uint32_t& r1, uint32_t& r2, uint32_t& r3, uint32_t addr) {
    asm volatile("ldmatrix.sync.aligned.m8n8.x4.shared.b16 {%0,%1,%2,%3}, [%4];"
        : "=r"(r0), "=r"(r1), "=r"(r2), "=r"(r3) : "r"(addr));
}
__device__ __forceinline__ void mma_f16(float* c, const uint32_t* a, uint32_t b0, uint32_t b1) {
    asm volatile("mma.sync.aligned.m16n8k16.row.col.f32.f16.f16.f32 "
        "{%0,%1,%2,%3}, {%4,%5,%6,%7}, {%8,%9}, {%0,%1,%2,%3};"
        : "+f"(c[0]), "+f"(c[1]), "+f"(c[2]), "+f"(c[3])
        : "r"(a[0]), "r"(a[1]), "r"(a[2]), "r"(a[3]), "r"(b0), "r"(b1));
}
__device__ __forceinline__ void cp_async16(uint32_t saddr, const void* gaddr) {
    asm volatile("cp.async.cg.shared.global [%0], [%1], 16;" :: "r"(saddr), "l"(gaddr));
}

// ---------------- prep: W (proj) -> fp16 ----------------
__global__ void __launch_bounds__(256) wsplit_kernel(const float* __restrict__ wproj)
{
    int idx = blockIdx.x * 256 + threadIdx.x;
    if (idx >= 5 * 65536) return;
    int b = idx >> 16, rem = idx & 65535;
    int m = rem >> 8, c = rem & 255;
    g_w[((size_t)b * 256 + m) * 256 + c] = __float2half(wproj[m * 1280 + b * 256 + c]);
}

// ---------------- prep: logits weights -> A[384][256] fp16 ----------------
__global__ void __launch_bounds__(256) wl2split_kernel(
    const float* __restrict__ wa, const float* __restrict__ wb,
    const float* __restrict__ wc, const float* __restrict__ wd)
{
    int idx = blockIdx.x * 256 + threadIdx.x;       // 384*256
    if (idx >= 98304) return;
    int c = idx & 255, m = idx >> 8;
    int br = m / 96, row = m - br * 96;
    float w = 0.f;
    if (row < 81) {
        int o = row / 9, tap = row - o * 9;
        const float* wp = (br == 0) ? wa : (br == 1) ? wb : (br == 2) ? wc : wd;
        w = wp[(o * 256 + c) * 9 + tap];
    }
    g_wl2[(size_t)m * 256 + c] = __float2half(w);
}

// ---------------- prep: transpose x to [p][c] fp16 ----------------
__global__ void __launch_bounds__(256) xsplit_kernel(const float* __restrict__ x)
{
    __shared__ float t[32][33];
    int p0 = blockIdx.x * 32, k0 = blockIdx.y * 32, n = blockIdx.z;
    int tx = threadIdx.x, ty = threadIdx.y;
#pragma unroll
    for (int r = 0; r < 4; r++)
        t[ty + 8 * r][tx] = x[((size_t)(n * 256 + k0 + ty + 8 * r)) * HW + p0 + tx];
    __syncthreads();
#pragma unroll
    for (int r = 0; r < 4; r++) {
        int p = p0 + ty + 8 * r, c = k0 + tx;
        g_xT[((size_t)n * HW + p) * 256 + c] = __float2half(t[tx][ty + 8 * r]);
    }
}

// ================= GEMM tile: 128m x 128p; K=256 in 4 chunks of 64 ==========
struct MmaCtx {
    uint32_t sbase;
    int tid, lane, warp_m, warp_n;
    float acc[4][4][4];
    __device__ __forceinline__ void init(uint32_t sb, int t) {
        sbase = sb; tid = t; lane = t & 31;
        int wid = t >> 5;
        warp_m = wid & 1; warp_n = wid >> 1;
#pragma unroll
        for (int i = 0; i < 4; i++)
#pragma unroll
            for (int j = 0; j < 4; j++)
#pragma unroll
                for (int r = 0; r < 4; r++) acc[i][j][r] = 0.f;
    }
    __device__ __forceinline__ void fill(int buf, const char* Ag, const char* Bg) {
        uint32_t aOff = buf * 32768u;
        uint32_t bOff = 16384u + buf * 32768u;
#pragma unroll
        for (int r = 0; r < 4; r++) {
            int idx = tid + 256 * r;
            int row = idx >> 3, u = idx & 7;
            uint32_t sw = row * 128 + ((u ^ (row & 7)) << 4);
            cp_async16(sbase + aOff + sw, Ag + (size_t)row * 512 + u * 16);
            cp_async16(sbase + bOff + sw, Bg + (size_t)row * 512 + u * 16);
        }
        asm volatile("cp.async.commit_group;");
    }
    __device__ __forceinline__ void compute(int buf) {
        uint32_t aB = sbase + buf * 32768u;
        uint32_t bB = sbase + 16384u + buf * 32768u;
#pragma unroll
        for (int ks = 0; ks < 4; ks++) {
            int u0 = ks * 2 + (lane >> 4);
            uint32_t a[4][4], bb[2][4];
#pragma unroll
            for (int q = 0; q < 2; q++) {
                int row = warp_n * 32 + q * 16 + (lane & 15);
                ldmatrix_x4(bb[q][0], bb[q][1], bb[q][2], bb[q][3],
                            bB + row * 128 + (((unsigned)(u0 ^ (row & 7))) << 4));
            }
#pragma unroll
            for (int mi = 0; mi < 4; mi++) {
                int row = warp_m * 64 + mi * 16 + (lane & 15);
                ldmatrix_x4(a[mi][0], a[mi][1], a[mi][2], a[mi][3],
                            aB + row * 128 + (((unsigned)(u0 ^ (row & 7))) << 4));
            }
#pragma unroll
            for (int mi = 0; mi < 4; mi++)
#pragma unroll
                for (int nj = 0; nj < 4; nj++) {
                    int q = nj >> 1, pr = nj & 1;
                    mma_f16(acc[mi][nj], a[mi], bb[q][pr], bb[q][pr + 2]);
                }
        }
    }
    __device__ __forceinline__ void run(const char* Abase, const char* Bbase) {
        fill(0, Abase, Bbase);
        fill(1, Abase + 128, Bbase + 128);
        for (int i = 0; i < 4; i++) {
            if (i < 3) asm volatile("cp.async.wait_group 1;");
            else       asm volatile("cp.async.wait_group 0;");
            __syncthreads();
            compute(i % 3);
            if (i + 2 < 4) fill((i + 2) % 3, Abase + (i + 2) * 128, Bbase + (i + 2) * 128);
        }
        __syncthreads();
    }
    __device__ __forceinline__ void stage_out(float* stage) {
#pragma unroll
        for (int mi = 0; mi < 4; mi++)
#pragma unroll
            for (int nj = 0; nj < 4; nj++)
#pragma unroll
                for (int r = 0; r < 4; r++) {
                    int p = warp_n * 32 + nj * 8 + 2 * (lane & 3) + (r & 1);
                    int m = warp_m * 64 + mi * 16 + (lane >> 2) + ((r >> 1) << 3);
                    stage[p * 132 + m] = acc[mi][nj][r];
                }
    }
};

// ---------------- 1) U-GEMM: grid (72, 3, 2) ----------------
__global__ void __launch_bounds__(256, 2) gemm_u_kernel()
{
    extern __shared__ char dsm[];
    MmaCtx g;
    g.init(smem_u32(dsm), threadIdx.x);
    int pbase = blockIdx.x * 128;
    int mbase = blockIdx.y * 128;
    int n = blockIdx.z;

    g.run((const char*)g_wl2 + (size_t)mbase * 512,
          (const char*)g_xT + ((size_t)n * HW + pbase) * 512);

    float* stage = (float*)dsm;
    g.stage_out(stage);
    __syncthreads();
#pragma unroll
    for (int rr = 0; rr < 16; rr++) {
        int idx = threadIdx.x + 256 * rr;
        int m = idx >> 5, p4 = (idx & 31) * 4;
        float4 v = make_float4(stage[p4 * 132 + m], stage[(p4 + 1) * 132 + m],
                               stage[(p4 + 2) * 132 + m], stage[(p4 + 3) * 132 + m]);
        *(float4*)(g_u + ((size_t)n * 384 + mbase + m) * HW + pbase + p4) = v;
    }
}

// ---------------- 2) gather taps + softmax ----------------
__global__ void __launch_bounds__(256) gathersoftmax_kernel()
{
    int id = blockIdx.x * 256 + threadIdx.x;
    int p = id % HW;
    int nb = id / HW;
    int n = nb >> 2, br = nb & 3;
    int d = (br == 0) ? 1 : (br == 1) ? 4 : (br == 2) ? 8 : 12;
    int y = p / 96, x = p - y * 96;

    int po[9];
#pragma unroll
    for (int t = 0; t < 9; t++) {
        int yy = y + (t / 3 - 1) * d;
        int xx = x + (t % 3 - 1) * d;
        po[t] = (((unsigned)yy < 96u) && ((unsigned)xx < 96u)) ? (yy * 96 + xx) : -1;
    }

    const float* ub = g_u + ((size_t)n * 384 + br * 96) * HW;
    float l[9];
#pragma unroll
    for (int o = 0; o < 9; o++) {
        float s = 0.f;
#pragma unroll
        for (int t = 0; t < 9; t++)
            if (po[t] >= 0) s += ub[(size_t)(o * 9 + t) * HW + po[t]];
        l[o] = s;
    }
    float m = l[0];
#pragma unroll
    for (int o = 1; o < 9; o++) m = fmaxf(m, l[o]);
    float s = 0.f;
#pragma unroll
    for (int o = 0; o < 9; o++) { l[o] = expf(l[o] - m); s += l[o]; }
    float inv = 1.f / s;
#pragma unroll
    for (int o = 0; o < 9; o++)
        g_f[((size_t)nb * 9 + o) * HW + p] = l[o] * inv;
}

// ---------------- 3) proj GEMM: grid (72, 2, 10), fp16 output ----------------
__global__ void __launch_bounds__(256, 2) gemm_mma_kernel()
{
    extern __shared__ char dsm[];
    MmaCtx g;
    g.init(smem_u32(dsm), threadIdx.x);
    int pbase = blockIdx.x * 128;
    int mbase = blockIdx.y * 128;
    int bn = blockIdx.z;
    int b = bn >> 1, n = bn & 1;

    g.run((const char*)g_w + ((size_t)b * 256 + mbase) * 512,
          (const char*)g_xT + ((size_t)n * HW + pbase) * 512);

    float* stage = (float*)dsm;
    g.stage_out(stage);
    __syncthreads();
    __half* zo = g_z + ((size_t)bn * HW + pbase) * 256 + mbase;
#pragma unroll
    for (int r = 0; r < 16; r++) {
        int idx = threadIdx.x + 256 * r;
        int px = idx >> 5, c4 = (idx & 31) * 4;
        float4 v = *(float4*)&stage[px * 132 + c4];
        __half2 lo = __floats2half2_rn(v.x, v.y);
        __half2 hi = __floats2half2_rn(v.z, v.w);
        uint2 pk;
        pk.x = *(uint32_t*)&lo;
        pk.y = *(uint32_t*)&hi;
        *(uint2*)(zo + (size_t)px * 256 + c4) = pk;
    }
}

// ---------------- 4) combine: one warp per pixel, fp16 z ----------------
// grid (576, 2), block 512 = 16 warps = 16 pixels; lane = one 8-ch GN group
__global__ void __launch_bounds__(512) combine_kernel(const float* __restrict__ bias)
{
    int tid = threadIdx.x;
    int n = blockIdx.y;
    int p0 = blockIdx.x * 16;
    int warp = tid >> 5, lane = tid & 31;
    int p = p0 + warp;
    int c8 = lane * 8;

    __shared__ float fsw[16][40];
    __shared__ int   pofs[16][40];
    __shared__ float ws[16][32];
    __shared__ float wq[16][32];

    for (int i = tid; i < 16 * 36; i += 512) {
        int pi2 = i / 36, j = i - pi2 * 36;
        int br = j / 9, k = j - br * 9;
        int d = (br == 0) ? 1 : (br == 1) ? 4 : (br == 2) ? 8 : 12;
        int pg = p0 + pi2;
        int yy = pg / 96 + (k / 3 - 1) * d;
        int xx = pg % 96 + (k % 3 - 1) * d;
        bool v = ((unsigned)yy < 96u) && ((unsigned)xx < 96u);
        fsw[pi2][j]  = v ? g_f[((size_t)(n * 4 + br) * 9 + k) * HW + pg] : 0.f;
        pofs[pi2][j] = (((br + 1) * 2 + n) * HW + (v ? (yy * 96 + xx) : 0)) * 256;
    }
    __syncthreads();

    float a[8];
    {
        float4 b0 = *(const float4*)(bias + c8);
        float4 b1 = *(const float4*)(bias + c8 + 4);
        uint4 zv = *(const uint4*)(g_z + ((size_t)n * HW + p) * 256 + c8);
        float2 f0 = __half22float2(*(__half2*)&zv.x);
        float2 f1 = __half22float2(*(__half2*)&zv.y);
        float2 f2 = __half22float2(*(__half2*)&zv.z);
        float2 f3 = __half22float2(*(__half2*)&zv.w);
        a[0] = f0.x + b0.x; a[1] = f0.y + b0.y; a[2] = f1.x + b0.z; a[3] = f1.y + b0.w;
        a[4] = f2.x + b1.x; a[5] = f2.y + b1.y; a[6] = f3.x + b1.z; a[7] = f3.y + b1.w;
    }

#pragma unroll 4
    for (int j = 0; j < 36; j++) {
        float f = fsw[warp][j];
        uint4 zv = *(const uint4*)(g_z + (size_t)pofs[warp][j] + c8);
        float2 f0 = __half22float2(*(__half2*)&zv.x);
        float2 f1 = __half22float2(*(__half2*)&zv.y);
        float2 f2 = __half22float2(*(__half2*)&zv.z);
        float2 f3 = __half22float2(*(__half2*)&zv.w);
        a[0] = fmaf(f, f0.x, a[0]); a[1] = fmaf(f, f0.y, a[1]);
        a[2] = fmaf(f, f1.x, a[2]); a[3] = fmaf(f, f1.y, a[3]);
        a[4] = fmaf(f, f2.x, a[4]); a[5] = fmaf(f, f2.y, a[5]);
        a[6] = fmaf(f, f3.x, a[6]); a[7] = fmaf(f, f3.y, a[7]);
    }

    float* yo = g_y + ((size_t)n * HW + p) * 256 + c8;
    *(float4*)yo       = make_float4(a[0], a[1], a[2], a[3]);
    *(float4*)(yo + 4) = make_float4(a[4], a[5], a[6], a[7]);

    float s = a[0] + a[1] + a[2] + a[3] + a[4] + a[5] + a[6] + a[7];
    float q = a[0]*a[0] + a[1]*a[1] + a[2]*a[2] + a[3]*a[3]
            + a[4]*a[4] + a[5]*a[5] + a[6]*a[6] + a[7]*a[7];
    ws[warp][lane] = s;
    wq[warp][lane] = q;
    __syncthreads();

    if (tid < 64) {
        int g = tid >> 1, isq = tid & 1;
        float acc = 0.f;
#pragma unroll
        for (int w = 0; w < 16; w++)
            acc += isq ? wq[w][g] : ws[w][g];
        g_bpart[((size_t)n * 576 + blockIdx.x) * 64 + tid] = acc;
    }
}

// ---------------- 5) GN stats ----------------
__global__ void __launch_bounds__(128) stats_kernel()
{
    int b = blockIdx.x;
    int n = b >> 5, g = b & 31;
    int tid = threadIdx.x;
    float s = 0.f, q = 0.f;
    for (int i = tid; i < 576; i += 128) {
        size_t base = ((size_t)n * 576 + i) * 64 + g * 2;
        s += g_bpart[base];
        q += g_bpart[base + 1];
    }
    __shared__ float ss[128], sq[128];
    ss[tid] = s; sq[tid] = q;
    __syncthreads();
    for (int off = 64; off > 0; off >>= 1) {
        if (tid < off) { ss[tid] += ss[tid + off]; sq[tid] += sq[tid + off]; }
        __syncthreads();
    }
    if (tid == 0) {
        const float invN = 1.f / 73728.f;
        float mean = ss[0] * invN;
        float var  = sq[0] * invN - mean * mean;
        g_stats[b * 2]     = mean;
        g_stats[b * 2 + 1] = rsqrtf(var + 1e-5f);
    }
}

// ---------------- 6) transpose + GN affine + relu ----------------
__global__ void __launch_bounds__(256) normT_kernel(
    const float* __restrict__ gamma, const float* __restrict__ beta,
    float* __restrict__ out)
{
    __shared__ float t[32][33];
    int p0 = blockIdx.x * 32, c0 = blockIdx.y * 32, n = blockIdx.z;
    int tx = threadIdx.x, ty = threadIdx.y;
#pragma unroll
    for (int r = 0; r < 4; r++)
        t[ty + 8 * r][tx] = g_y[((size_t)n * HW + p0 + ty + 8 * r) * 256 + c0 + tx];
    __syncthreads();
#pragma unroll
    for (int r = 0; r < 4; r++) {
        int c = c0 + ty + 8 * r, p = p0 + tx;
        int g = c >> 3;
        float mean = g_stats[(n * 32 + g) * 2];
        float rstd = g_stats[(n * 32 + g) * 2 + 1];
        float ga = gamma[c] * rstd;
        float be = beta[c] - mean * ga;
        float v = t[tx][ty + 8 * r];
        out[((size_t)n * 256 + c) * HW + p] = fmaxf(fmaf(v, ga, be), 0.f);
    }
}

// ---------------- launch ----------------
extern "C" void kernel_launch(void* const* d_in, const int* in_sizes, int n_in,
                              void* d_out, int out_size)
{
    const float* x     = (const float*)d_in[0];
    const float* wa    = (const float*)d_in[1];
    const float* wb    = (const float*)d_in[2];
    const float* wc    = (const float*)d_in[3];
    const float* wd    = (const float*)d_in[4];
    const float* wproj = (const float*)d_in[5];
    const float* bproj = (const float*)d_in[6];
    const float* gamma = (const float*)d_in[7];
    const float* beta  = (const float*)d_in[8];
    float* out = (float*)d_out;

    cudaFuncSetAttribute(gemm_mma_kernel, cudaFuncAttributeMaxDynamicSharedMemorySize, 98304);
    cudaFuncSetAttribute(gemm_u_kernel,   cudaFuncAttributeMaxDynamicSharedMemorySize, 98304);

    wsplit_kernel<<<1280, 256>>>(wproj);
    wl2split_kernel<<<384, 256>>>(wa, wb, wc, wd);
    xsplit_kernel<<<dim3(288, 8, 2), dim3(32, 8)>>>(x);
    gemm_u_kernel<<<dim3(72, 3, 2), 256, 98304>>>();
    gathersoftmax_kernel<<<288, 256>>>();
    gemm_mma_kernel<<<dim3(72, 2, 10), 256, 98304>>>();
    combine_kernel<<<dim3(576, 2), 512>>>(bproj);
    stats_kernel<<<64, 128>>>();
    normT_kernel<<<dim3(288, 8, 2), dim3(32, 8)>>>(gamma, beta, out);
}

// round 15
// speedup vs baseline: 1.8517x; 1.0174x over previous
#include <cuda_runtime.h>
#include <cuda_fp16.h>
#include <cstdint>
#include <math.h>

#define HW    9216
#define CH    256
#define NB    2

// ---------------- scratch ----------------
__device__ float g_f[8ull * 9 * HW];               // [nb][o][HW] softmax tap weights
__device__ float g_u[(size_t)NB * 384 * HW];       // [n][br*96 + o*9+tap][HW]
__device__ __half g_z[10ull * HW * CH + 400000];   // [b*2+n][p][c]  fp16
__device__ __half g_y[(size_t)NB * HW * CH];       // [n][p][c] fp16
__device__ float g_bpart[NB * 1152 * 64];
__device__ float g_stats[NB * 32 * 2];
__device__ __half g_w[5ull * 256 * 256];           // [b][m][c] fp16(w)
__device__ __half g_xT[(size_t)NB * HW * 256];     // [n][p][c] fp16(x)
__device__ __half g_wl2[384ull * 256];             // [m][c] fp16 logits weights

// ---------------- helpers ----------------
__device__ __forceinline__ uint32_t smem_u32(const void* p) {
    uint32_t a;
    asm("{ .reg .u64 t; cvta.to.shared.u64 t, %1; cvt.u32.u64 %0, t; }" : "=r"(a) : "l"(p));
    return a;
}
__device__ __forceinline__ void ldmatrix_x4(uint32_t& r0, uint32_t& r1, uint32_t& r2, uint32_t& r3, uint32_t addr) {
    asm volatile("ldmatrix.sync.aligned.m8n8.x4.shared.b16 {%0,%1,%2,%3}, [%4];"
        : "=r"(r0), "=r"(r1), "=r"(r2), "=r"(r3) : "r"(addr));
}
__device__ __forceinline__ void mma_f16(float* c, const uint32_t* a, uint32_t b0, uint32_t b1) {
    asm volatile("mma.sync.aligned.m16n8k16.row.col.f32.f16.f16.f32 "
        "{%0,%1,%2,%3}, {%4,%5,%6,%7}, {%8,%9}, {%0,%1,%2,%3};"
        : "+f"(c[0]), "+f"(c[1]), "+f"(c[2]), "+f"(c[3])
        : "r"(a[0]), "r"(a[1]), "r"(a[2]), "r"(a[3]), "r"(b0), "r"(b1));
}
__device__ __forceinline__ void cp_async16(uint32_t saddr, const void* gaddr) {
    asm volatile("cp.async.cg.shared.global [%0], [%1], 16;" :: "r"(saddr), "l"(gaddr));
}

// ---------------- prep: W (proj) -> fp16 ----------------
__global__ void __launch_bounds__(256) wsplit_kernel(const float* __restrict__ wproj)
{
    int idx = blockIdx.x * 256 + threadIdx.x;
    if (idx >= 5 * 65536) return;
    int b = idx >> 16, rem = idx & 65535;
    int m = rem >> 8, c = rem & 255;
    g_w[((size_t)b * 256 + m) * 256 + c] = __float2half(wproj[m * 1280 + b * 256 + c]);
}

// ---------------- prep: logits weights -> A[384][256] fp16 ----------------
__global__ void __launch_bounds__(256) wl2split_kernel(
    const float* __restrict__ wa, const float* __restrict__ wb,
    const float* __restrict__ wc, const float* __restrict__ wd)
{
    int idx = blockIdx.x * 256 + threadIdx.x;       // 384*256
    if (idx >= 98304) return;
    int c = idx & 255, m = idx >> 8;
    int br = m / 96, row = m - br * 96;
    float w = 0.f;
    if (row < 81) {
        int o = row / 9, tap = row - o * 9;
        const float* wp = (br == 0) ? wa : (br == 1) ? wb : (br == 2) ? wc : wd;
        w = wp[(o * 256 + c) * 9 + tap];
    }
    g_wl2[(size_t)m * 256 + c] = __float2half(w);
}

// ---------------- prep: transpose x to [p][c] fp16 ----------------
__global__ void __launch_bounds__(256) xsplit_kernel(const float* __restrict__ x)
{
    __shared__ float t[32][33];
    int p0 = blockIdx.x * 32, k0 = blockIdx.y * 32, n = blockIdx.z;
    int tx = threadIdx.x, ty = threadIdx.y;
#pragma unroll
    for (int r = 0; r < 4; r++)
        t[ty + 8 * r][tx] = x[((size_t)(n * 256 + k0 + ty + 8 * r)) * HW + p0 + tx];
    __syncthreads();
#pragma unroll
    for (int r = 0; r < 4; r++) {
        int p = p0 + ty + 8 * r, c = k0 + tx;
        g_xT[((size_t)n * HW + p) * 256 + c] = __float2half(t[tx][ty + 8 * r]);
    }
}

// ================= GEMM tile: 128m x 128p; K=256 in 4 chunks of 64 ==========
struct MmaCtx {
    uint32_t sbase;
    int tid, lane, warp_m, warp_n;
    float acc[4][4][4];
    __device__ __forceinline__ void init(uint32_t sb, int t) {
        sbase = sb; tid = t; lane = t & 31;
        int wid = t >> 5;
        warp_m = wid & 1; warp_n = wid >> 1;
#pragma unroll
        for (int i = 0; i < 4; i++)
#pragma unroll
            for (int j = 0; j < 4; j++)
#pragma unroll
                for (int r = 0; r < 4; r++) acc[i][j][r] = 0.f;
    }
    __device__ __forceinline__ void fill(int buf, const char* Ag, const char* Bg) {
        uint32_t aOff = buf * 32768u;
        uint32_t bOff = 16384u + buf * 32768u;
#pragma unroll
        for (int r = 0; r < 4; r++) {
            int idx = tid + 256 * r;
            int row = idx >> 3, u = idx & 7;
            uint32_t sw = row * 128 + ((u ^ (row & 7)) << 4);
            cp_async16(sbase + aOff + sw, Ag + (size_t)row * 512 + u * 16);
            cp_async16(sbase + bOff + sw, Bg + (size_t)row * 512 + u * 16);
        }
        asm volatile("cp.async.commit_group;");
    }
    __device__ __forceinline__ void compute(int buf) {
        uint32_t aB = sbase + buf * 32768u;
        uint32_t bB = sbase + 16384u + buf * 32768u;
#pragma unroll
        for (int ks = 0; ks < 4; ks++) {
            int u0 = ks * 2 + (lane >> 4);
            uint32_t a[4][4], bb[2][4];
#pragma unroll
            for (int q = 0; q < 2; q++) {
                int row = warp_n * 32 + q * 16 + (lane & 15);
                ldmatrix_x4(bb[q][0], bb[q][1], bb[q][2], bb[q][3],
                            bB + row * 128 + (((unsigned)(u0 ^ (row & 7))) << 4));
            }
#pragma unroll
            for (int mi = 0; mi < 4; mi++) {
                int row = warp_m * 64 + mi * 16 + (lane & 15);
                ldmatrix_x4(a[mi][0], a[mi][1], a[mi][2], a[mi][3],
                            aB + row * 128 + (((unsigned)(u0 ^ (row & 7))) << 4));
            }
#pragma unroll
            for (int mi = 0; mi < 4; mi++)
#pragma unroll
                for (int nj = 0; nj < 4; nj++) {
                    int q = nj >> 1, pr = nj & 1;
                    mma_f16(acc[mi][nj], a[mi], bb[q][pr], bb[q][pr + 2]);
                }
        }
    }
    __device__ __forceinline__ void run(const char* Abase, const char* Bbase) {
        fill(0, Abase, Bbase);
        fill(1, Abase + 128, Bbase + 128);
        for (int i = 0; i < 4; i++) {
            if (i < 3) asm volatile("cp.async.wait_group 1;");
            else       asm volatile("cp.async.wait_group 0;");
            __syncthreads();
            compute(i % 3);
            if (i + 2 < 4) fill((i + 2) % 3, Abase + (i + 2) * 128, Bbase + (i + 2) * 128);
        }
        __syncthreads();
    }
    __device__ __forceinline__ void stage_out(float* stage) {
#pragma unroll
        for (int mi = 0; mi < 4; mi++)
#pragma unroll
            for (int nj = 0; nj < 4; nj++)
#pragma unroll
                for (int r = 0; r < 4; r++) {
                    int p = warp_n * 32 + nj * 8 + 2 * (lane & 3) + (r & 1);
                    int m = warp_m * 64 + mi * 16 + (lane >> 2) + ((r >> 1) << 3);
                    stage[p * 132 + m] = acc[mi][nj][r];
                }
    }
};

// ---------------- 1+3) merged GEMM: grid (72, 13, 2) ----------------
// y 0..2  : U-tile  (A = g_wl2 + y*128 rows)      -> g_u[m][p] fp32
// y 3..12 : proj    (b = (y-3)>>1, mh = (y-3)&1)  -> g_z[bn][p][c] fp16
__global__ void __launch_bounds__(256, 2) gemm_all_kernel()
{
    extern __shared__ char dsm[];
    MmaCtx g;
    g.init(smem_u32(dsm), threadIdx.x);
    int pbase = blockIdx.x * 128;
    int iy = blockIdx.y;
    int n = blockIdx.z;

    const char* Bsrc = (const char*)g_xT + ((size_t)n * HW + pbase) * 512;
    float* stage = (float*)dsm;

    if (iy < 3) {
        int mbase = iy * 128;
        g.run((const char*)g_wl2 + (size_t)mbase * 512, Bsrc);
        g.stage_out(stage);
        __syncthreads();
#pragma unroll
        for (int rr = 0; rr < 16; rr++) {
            int idx = threadIdx.x + 256 * rr;
            int m = idx >> 5, p4 = (idx & 31) * 4;
            float4 v = make_float4(stage[p4 * 132 + m], stage[(p4 + 1) * 132 + m],
                                   stage[(p4 + 2) * 132 + m], stage[(p4 + 3) * 132 + m]);
            *(float4*)(g_u + ((size_t)n * 384 + mbase + m) * HW + pbase + p4) = v;
        }
    } else {
        int idx2 = iy - 3;
        int b = idx2 >> 1, mh = idx2 & 1;
        int mbase = mh * 128;
        g.run((const char*)g_w + ((size_t)b * 256 + mbase) * 512, Bsrc);
        g.stage_out(stage);
        __syncthreads();
        __half* zo = g_z + ((size_t)(b * 2 + n) * HW + pbase) * 256 + mbase;
#pragma unroll
        for (int r = 0; r < 16; r++) {
            int idx = threadIdx.x + 256 * r;
            int px = idx >> 5, c4 = (idx & 31) * 4;
            float4 v = *(float4*)&stage[px * 132 + c4];
            __half2 lo = __floats2half2_rn(v.x, v.y);
            __half2 hi = __floats2half2_rn(v.z, v.w);
            uint2 pk;
            pk.x = *(uint32_t*)&lo;
            pk.y = *(uint32_t*)&hi;
            *(uint2*)(zo + (size_t)px * 256 + c4) = pk;
        }
    }
}

// ---------------- 2) gather taps + softmax ----------------
__global__ void __launch_bounds__(256) gathersoftmax_kernel()
{
    int id = blockIdx.x * 256 + threadIdx.x;
    int p = id % HW;
    int nb = id / HW;
    int n = nb >> 2, br = nb & 3;
    int d = (br == 0) ? 1 : (br == 1) ? 4 : (br == 2) ? 8 : 12;
    int y = p / 96, x = p - y * 96;

    int po[9];
#pragma unroll
    for (int t = 0; t < 9; t++) {
        int yy = y + (t / 3 - 1) * d;
        int xx = x + (t % 3 - 1) * d;
        po[t] = (((unsigned)yy < 96u) && ((unsigned)xx < 96u)) ? (yy * 96 + xx) : -1;
    }

    const float* ub = g_u + ((size_t)n * 384 + br * 96) * HW;
    float l[9];
#pragma unroll
    for (int o = 0; o < 9; o++) {
        float s = 0.f;
#pragma unroll
        for (int t = 0; t < 9; t++)
            if (po[t] >= 0) s += ub[(size_t)(o * 9 + t) * HW + po[t]];
        l[o] = s;
    }
    float m = l[0];
#pragma unroll
    for (int o = 1; o < 9; o++) m = fmaxf(m, l[o]);
    float s = 0.f;
#pragma unroll
    for (int o = 0; o < 9; o++) { l[o] = expf(l[o] - m); s += l[o]; }
    float inv = 1.f / s;
#pragma unroll
    for (int o = 0; o < 9; o++)
        g_f[((size_t)nb * 9 + o) * HW + p] = l[o] * inv;
}

// ---------------- 4) combine: one warp per pixel, fp16 z, fp16 y ----------------
__global__ void __launch_bounds__(512) combine_kernel(const float* __restrict__ bias)
{
    int tid = threadIdx.x;
    int n = blockIdx.y;
    int p0 = blockIdx.x * 16;
    int warp = tid >> 5, lane = tid & 31;
    int p = p0 + warp;
    int c8 = lane * 8;

    __shared__ float fsw[16][40];
    __shared__ int   pofs[16][40];
    __shared__ float ws[16][32];
    __shared__ float wq[16][32];

    for (int i = tid; i < 16 * 36; i += 512) {
        int pi2 = i / 36, j = i - pi2 * 36;
        int br = j / 9, k = j - br * 9;
        int d = (br == 0) ? 1 : (br == 1) ? 4 : (br == 2) ? 8 : 12;
        int pg = p0 + pi2;
        int yy = pg / 96 + (k / 3 - 1) * d;
        int xx = pg % 96 + (k % 3 - 1) * d;
        bool v = ((unsigned)yy < 96u) && ((unsigned)xx < 96u);
        fsw[pi2][j]  = v ? g_f[((size_t)(n * 4 + br) * 9 + k) * HW + pg] : 0.f;
        pofs[pi2][j] = (((br + 1) * 2 + n) * HW + (v ? (yy * 96 + xx) : 0)) * 256;
    }
    __syncthreads();

    float a[8];
    {
        float4 b0 = *(const float4*)(bias + c8);
        float4 b1 = *(const float4*)(bias + c8 + 4);
        uint4 zv = *(const uint4*)(g_z + ((size_t)n * HW + p) * 256 + c8);
        float2 f0 = __half22float2(*(__half2*)&zv.x);
        float2 f1 = __half22float2(*(__half2*)&zv.y);
        float2 f2 = __half22float2(*(__half2*)&zv.z);
        float2 f3 = __half22float2(*(__half2*)&zv.w);
        a[0] = f0.x + b0.x; a[1] = f0.y + b0.y; a[2] = f1.x + b0.z; a[3] = f1.y + b0.w;
        a[4] = f2.x + b1.x; a[5] = f2.y + b1.y; a[6] = f3.x + b1.z; a[7] = f3.y + b1.w;
    }

#pragma unroll 4
    for (int j = 0; j < 36; j++) {
        float f = fsw[warp][j];
        uint4 zv = *(const uint4*)(g_z + (size_t)pofs[warp][j] + c8);
        float2 f0 = __half22float2(*(__half2*)&zv.x);
        float2 f1 = __half22float2(*(__half2*)&zv.y);
        float2 f2 = __half22float2(*(__half2*)&zv.z);
        float2 f3 = __half22float2(*(__half2*)&zv.w);
        a[0] = fmaf(f, f0.x, a[0]); a[1] = fmaf(f, f0.y, a[1]);
        a[2] = fmaf(f, f1.x, a[2]); a[3] = fmaf(f, f1.y, a[3]);
        a[4] = fmaf(f, f2.x, a[4]); a[5] = fmaf(f, f2.y, a[5]);
        a[6] = fmaf(f, f3.x, a[6]); a[7] = fmaf(f, f3.y, a[7]);
    }

    // store y fp16 (stats use fp32 values below)
    {
        __half2 h0 = __floats2half2_rn(a[0], a[1]);
        __half2 h1 = __floats2half2_rn(a[2], a[3]);
        __half2 h2 = __floats2half2_rn(a[4], a[5]);
        __half2 h3 = __floats2half2_rn(a[6], a[7]);
        uint4 pk;
        pk.x = *(uint32_t*)&h0; pk.y = *(uint32_t*)&h1;
        pk.z = *(uint32_t*)&h2; pk.w = *(uint32_t*)&h3;
        *(uint4*)(g_y + ((size_t)n * HW + p) * 256 + c8) = pk;
    }

    float s = a[0] + a[1] + a[2] + a[3] + a[4] + a[5] + a[6] + a[7];
    float q = a[0]*a[0] + a[1]*a[1] + a[2]*a[2] + a[3]*a[3]
            + a[4]*a[4] + a[5]*a[5] + a[6]*a[6] + a[7]*a[7];
    ws[warp][lane] = s;
    wq[warp][lane] = q;
    __syncthreads();

    if (tid < 64) {
        int g = tid >> 1, isq = tid & 1;
        float acc = 0.f;
#pragma unroll
        for (int w = 0; w < 16; w++)
            acc += isq ? wq[w][g] : ws[w][g];
        g_bpart[((size_t)n * 576 + blockIdx.x) * 64 + tid] = acc;
    }
}

// ---------------- 5) GN stats ----------------
__global__ void __launch_bounds__(128) stats_kernel()
{
    int b = blockIdx.x;
    int n = b >> 5, g = b & 31;
    int tid = threadIdx.x;
    float s = 0.f, q = 0.f;
    for (int i = tid; i < 576; i += 128) {
        size_t base = ((size_t)n * 576 + i) * 64 + g * 2;
        s += g_bpart[base];
        q += g_bpart[base + 1];
    }
    __shared__ float ss[128], sq[128];
    ss[tid] = s; sq[tid] = q;
    __syncthreads();
    for (int off = 64; off > 0; off >>= 1) {
        if (tid < off) { ss[tid] += ss[tid + off]; sq[tid] += sq[tid + off]; }
        __syncthreads();
    }
    if (tid == 0) {
        const float invN = 1.f / 73728.f;
        float mean = ss[0] * invN;
        float var  = sq[0] * invN - mean * mean;
        g_stats[b * 2]     = mean;
        g_stats[b * 2 + 1] = rsqrtf(var + 1e-5f);
    }
}

// ---------------- 6) transpose + GN affine + relu (fp16 y in) ----------------
__global__ void __launch_bounds__(256) normT_kernel(
    const float* __restrict__ gamma, const float* __restrict__ beta,
    float* __restrict__ out)
{
    __shared__ float t[32][33];
    int p0 = blockIdx.x * 32, c0 = blockIdx.y * 32, n = blockIdx.z;
    int tx = threadIdx.x, ty = threadIdx.y;
#pragma unroll
    for (int r = 0; r < 4; r++)
        t[ty + 8 * r][tx] = __half2float(g_y[((size_t)n * HW + p0 + ty + 8 * r) * 256 + c0 + tx]);
    __syncthreads();
#pragma unroll
    for (int r = 0; r < 4; r++) {
        int c = c0 + ty + 8 * r, p = p0 + tx;
        int g = c >> 3;
        float mean = g_stats[(n * 32 + g) * 2];
        float rstd = g_stats[(n * 32 + g) * 2 + 1];
        float ga = gamma[c] * rstd;
        float be = beta[c] - mean * ga;
        float v = t[tx][ty + 8 * r];
        out[((size_t)n * 256 + c) * HW + p] = fmaxf(fmaf(v, ga, be), 0.f);
    }
}

// ---------------- launch ----------------
extern "C" void kernel_launch(void* const* d_in, const int* in_sizes, int n_in,
                              void* d_out, int out_size)
{
    const float* x     = (const float*)d_in[0];
    const float* wa    = (const float*)d_in[1];
    const float* wb    = (const float*)d_in[2];
    const float* wc    = (const float*)d_in[3];
    const float* wd    = (const float*)d_in[4];
    const float* wproj = (const float*)d_in[5];
    const float* bproj = (const float*)d_in[6];
    const float* gamma = (const float*)d_in[7];
    const float* beta  = (const float*)d_in[8];
    float* out = (float*)d_out;

    cudaFuncSetAttribute(gemm_all_kernel, cudaFuncAttributeMaxDynamicSharedMemorySize, 98304);

    wsplit_kernel<<<1280, 256>>>(wproj);
    wl2split_kernel<<<384, 256>>>(wa, wb, wc, wd);
    xsplit_kernel<<<dim3(288, 8, 2), dim3(32, 8)>>>(x);
    gemm_all_kernel<<<dim3(72, 13, 2), 256, 98304>>>();
    gathersoftmax_kernel<<<288, 256>>>();
    combine_kernel<<<dim3(576, 2), 512>>>(bproj);
    stats_kernel<<<64, 128>>>();
    normT_kernel<<<dim3(288, 8, 2), dim3(32, 8)>>>(gamma, beta, out);
}